// round 7
// baseline (speedup 1.0000x reference)
#include <cuda_runtime.h>
#include <math.h>

#define B_TOT 128
#define NWIN  32
#define NTOK  343
#define HEADS 6
#define HD    32
#define CDIM  192
#define C3    576
#define MTOT  (B_TOT * NTOK)   // 43904
#define JPAD  384
#define L2E   1.4426950408889634f

// Scratch (no allocations allowed)
__device__ float g_qkv[MTOT * C3];                     // 101.2 MB
__device__ float g_ao [MTOT * CDIM];                   //  33.7 MB
__device__ float g_biasp[HEADS * NTOK * JPAD];         //   3.2 MB (L2-resident, *L2E, padded)
__device__ float g_maskp[NWIN  * NTOK * JPAD];         //  16.9 MB (L2-resident, *L2E, padded)

// ---------------------------------------------------------------------------
// tf32 helpers
// ---------------------------------------------------------------------------
__device__ __forceinline__ unsigned f2tf(float x) {
    unsigned r; asm("cvt.rna.tf32.f32 %0, %1;" : "=r"(r) : "f"(x)); return r;
}
__device__ __forceinline__ void mma8(float* c, const unsigned* a, const unsigned* b) {
    asm("mma.sync.aligned.m16n8k8.row.col.f32.tf32.tf32.f32 "
        "{%0,%1,%2,%3}, {%4,%5,%6,%7}, {%8,%9}, {%0,%1,%2,%3};"
        : "+f"(c[0]), "+f"(c[1]), "+f"(c[2]), "+f"(c[3])
        : "r"(a[0]), "r"(a[1]), "r"(a[2]), "r"(a[3]), "r"(b[0]), "r"(b[1]));
}

// ---------------------------------------------------------------------------
// Precompute padded, log2e-scaled bias and mask tables
// ---------------------------------------------------------------------------
__global__ void padb_kernel(const float* __restrict__ table,
                            const int* __restrict__ rel) {
    int idx = blockIdx.x * blockDim.x + threadIdx.x;
    if (idx >= HEADS * NTOK * JPAD) return;
    int j  = idx % JPAD;
    int hi = idx / JPAD;
    int i  = hi % NTOK, h = hi / NTOK;
    g_biasp[idx] = (j < NTOK) ? table[rel[i * NTOK + j] * HEADS + h] * L2E : -1e30f;
}
__global__ void padm_kernel(const float* __restrict__ mask) {
    int idx = blockIdx.x * blockDim.x + threadIdx.x;
    if (idx >= NWIN * NTOK * JPAD) return;
    int j  = idx % JPAD;
    int wi = idx / JPAD;
    int i  = wi % NTOK, w = wi / NTOK;
    g_maskp[idx] = (j < NTOK) ? mask[((size_t)w * NTOK + i) * NTOK + j] * L2E : -1e30f;
}

// ---------------------------------------------------------------------------
// Pipelined tensor-core GEMM (unchanged from R6)
// ---------------------------------------------------------------------------
#define BM 128
#define BN 64
#define BK 16
#define SA_STR 136
#define SB_STR 72

template<int K>
__global__ __launch_bounds__(256) void gemm_tc(const float* __restrict__ X,
                                               const float* __restrict__ W,
                                               const float* __restrict__ bias,
                                               float* __restrict__ C,
                                               int M, int N) {
    __shared__ unsigned sA[2][BK][SA_STR];
    __shared__ unsigned sB[2][BK][SB_STR];
    const int m0 = blockIdx.y * BM, n0 = blockIdx.x * BN;
    const int t = threadIdx.x, lane = t & 31, warp = t >> 5;
    const int wm = warp >> 1, wn = warp & 1;
    const int grp = lane >> 2, tig = lane & 3;
    const int lr  = t >> 2;
    const int lk4 = (t & 3) * 4;

    const float* pA0 = &X[(size_t)(m0 + lr) * K + lk4];
    const float* pA1 = &X[(size_t)(m0 + lr + 64) * K + lk4];
    const float* pB  = &W[(size_t)(n0 + lr) * K + lk4];

    float4 ra0 = *(const float4*)pA0;
    float4 ra1 = *(const float4*)pA1;
    float4 rb  = *(const float4*)pB;
    {
        sA[0][lk4+0][lr] = f2tf(ra0.x); sA[0][lk4+1][lr] = f2tf(ra0.y);
        sA[0][lk4+2][lr] = f2tf(ra0.z); sA[0][lk4+3][lr] = f2tf(ra0.w);
        sA[0][lk4+0][lr+64] = f2tf(ra1.x); sA[0][lk4+1][lr+64] = f2tf(ra1.y);
        sA[0][lk4+2][lr+64] = f2tf(ra1.z); sA[0][lk4+3][lr+64] = f2tf(ra1.w);
        sB[0][lk4+0][lr] = f2tf(rb.x); sB[0][lk4+1][lr] = f2tf(rb.y);
        sB[0][lk4+2][lr] = f2tf(rb.z); sB[0][lk4+3][lr] = f2tf(rb.w);
    }
    __syncthreads();

    float acc[2][4][4] = {};
    constexpr int NCH = K / BK;

    #pragma unroll
    for (int ch = 0; ch < NCH; ch++) {
        const int p = ch & 1;
        if (ch + 1 < NCH) {
            ra0 = *(const float4*)(pA0 + (ch + 1) * BK);
            ra1 = *(const float4*)(pA1 + (ch + 1) * BK);
            rb  = *(const float4*)(pB  + (ch + 1) * BK);
        }
        #pragma unroll
        for (int ks = 0; ks < 2; ks++) {
            const int kk = ks * 8 + tig;
            unsigned af[2][4], bf[4][2];
            #pragma unroll
            for (int mt = 0; mt < 2; mt++) {
                int r = wm * 32 + mt * 16 + grp;
                af[mt][0] = sA[p][kk][r];     af[mt][1] = sA[p][kk][r + 8];
                af[mt][2] = sA[p][kk+4][r];   af[mt][3] = sA[p][kk+4][r + 8];
            }
            #pragma unroll
            for (int nt = 0; nt < 4; nt++) {
                int n = wn * 32 + nt * 8 + grp;
                bf[nt][0] = sB[p][kk][n];
                bf[nt][1] = sB[p][kk+4][n];
            }
            #pragma unroll
            for (int mt = 0; mt < 2; mt++)
                #pragma unroll
                for (int nt = 0; nt < 4; nt++)
                    mma8(acc[mt][nt], af[mt], bf[nt]);
        }
        if (ch + 1 < NCH) {
            const int q = 1 - p;
            sA[q][lk4+0][lr] = f2tf(ra0.x); sA[q][lk4+1][lr] = f2tf(ra0.y);
            sA[q][lk4+2][lr] = f2tf(ra0.z); sA[q][lk4+3][lr] = f2tf(ra0.w);
            sA[q][lk4+0][lr+64] = f2tf(ra1.x); sA[q][lk4+1][lr+64] = f2tf(ra1.y);
            sA[q][lk4+2][lr+64] = f2tf(ra1.z); sA[q][lk4+3][lr+64] = f2tf(ra1.w);
            sB[q][lk4+0][lr] = f2tf(rb.x); sB[q][lk4+1][lr] = f2tf(rb.y);
            sB[q][lk4+2][lr] = f2tf(rb.z); sB[q][lk4+3][lr] = f2tf(rb.w);
            __syncthreads();
        }
    }
    #pragma unroll
    for (int mt = 0; mt < 2; mt++) {
        #pragma unroll
        for (int nt = 0; nt < 4; nt++) {
            int r = m0 + wm * 32 + mt * 16 + grp;
            int n = n0 + wn * 32 + nt * 8 + 2 * tig;
            float b0 = bias[n], b1 = bias[n + 1];
            *(float2*)&C[(size_t)r * N + n] =
                make_float2(acc[mt][nt][0] + b0, acc[mt][nt][1] + b1);
            *(float2*)&C[(size_t)(r + 8) * N + n] =
                make_float2(acc[mt][nt][2] + b0, acc[mt][nt][3] + b1);
        }
    }
}

// ---------------------------------------------------------------------------
// Flash attention, R7: sK XOR-swizzled (kills 8-way conflict on QK bf loads),
// all staging stores vectorized to STS.128
// ---------------------------------------------------------------------------
#define QT    128
#define SKSTR 36
#define SVSTR 40
#define PSTR  68
#define FLASH_SMEM_BYTES ((128*PSTR + 64*SKSTR + 64*SVSTR) * 4)

__global__ __launch_bounds__(256, 2) void attn_flash(const float* __restrict__ qkv,
                                                     float* __restrict__ ao) {
    extern __shared__ float sm[];
    float* sP = sm;                  // [128][68]: Q staging, then bias+mask / P
    float* sK = sP + 128 * PSTR;     // [64][36] XOR-swizzled: (r,d) at r*36 + (d ^ ((r&7)<<2))
    float* sV = sK + 64 * SKSTR;     // [64][40]
    unsigned* uP = (unsigned*)sP;
    unsigned* uK = (unsigned*)sK;
    unsigned* uV = (unsigned*)sV;

    const int bh = blockIdx.y, b = bh / HEADS, h = bh % HEADS;
    const int q0 = blockIdx.x * QT;
    const int w = b % NWIN;
    const int t = threadIdx.x, lane = t & 31, warp = t >> 5;
    const int grp = lane >> 2, tig = lane & 3;
    const float qs = 0.17677669529663687f * L2E;   // hd^-0.5 * log2(e)

    // ---- stage Q (scaled, tf32) into sP region, stride 36, STS.128 ----
    #pragma unroll
    for (int it = 0; it < 4; it++) {
        int f = it * 256 + t;
        int r = f >> 3, d = (f & 7) * 4;
        int n = q0 + r;
        float4 v = make_float4(0.f, 0.f, 0.f, 0.f);
        if (n < NTOK) v = *(const float4*)&qkv[(size_t)(b * NTOK + n) * C3 + h * HD + d];
        *(uint4*)&uP[r * 36 + d] = make_uint4(f2tf(v.x * qs), f2tf(v.y * qs),
                                              f2tf(v.z * qs), f2tf(v.w * qs));
    }
    __syncthreads();

    // ---- Q fragments (warp owns rows warp*16 .. +15) ----
    unsigned aq[4][4];
    const int qr = warp * 16 + grp;
    #pragma unroll
    for (int ks = 0; ks < 4; ks++) {
        int kk = ks * 8 + tig;
        aq[ks][0] = uP[qr * 36 + kk];
        aq[ks][1] = uP[(qr + 8) * 36 + kk];
        aq[ks][2] = uP[qr * 36 + kk + 4];
        aq[ks][3] = uP[(qr + 8) * 36 + kk + 4];
    }
    __syncthreads();   // sP free for bias+mask staging

    float oacc[4][4] = {};
    float mrow[2] = {-1e30f, -1e30f};
    float lrow[2] = {0.f, 0.f};

    const float* biasp = g_biasp + (size_t)h * NTOK * JPAD;
    const float* maskp = g_maskp + (size_t)w * NTOK * JPAD;

    for (int kt = 0; kt < 6; kt++) {
        const int k0 = kt * 64;
        // ---- stage K (swizzled) and V tiles, STS.128 ----
        #pragma unroll
        for (int it = 0; it < 2; it++) {
            int f = it * 256 + t;
            int r = f >> 3, d = (f & 7) * 4;
            int n = k0 + r;
            float4 kv = make_float4(0.f, 0.f, 0.f, 0.f);
            float4 vv = make_float4(0.f, 0.f, 0.f, 0.f);
            if (n < NTOK) {
                kv = *(const float4*)&qkv[(size_t)(b * NTOK + n) * C3 + CDIM + h * HD + d];
                vv = *(const float4*)&qkv[(size_t)(b * NTOK + n) * C3 + 2 * CDIM + h * HD + d];
            }
            int sw = (r & 7) << 2;
            *(uint4*)&uK[r * SKSTR + (d ^ sw)] = make_uint4(f2tf(kv.x), f2tf(kv.y),
                                                            f2tf(kv.z), f2tf(kv.w));
            *(uint4*)&uV[r * SVSTR + d] = make_uint4(f2tf(vv.x), f2tf(vv.y),
                                                     f2tf(vv.z), f2tf(vv.w));
        }
        // ---- stage (bias+mask) tile (padded, pre-scaled, float4) ----
        #pragma unroll
        for (int it = 0; it < 8; it++) {
            int f = it * 256 + t;               // 2048 float4s
            int r = f >> 4, c4 = (f & 15) * 4;
            int i = q0 + r; if (i > NTOK - 1) i = NTOK - 1;
            float4 bv = *(const float4*)&biasp[i * JPAD + k0 + c4];
            float4 mv = *(const float4*)&maskp[i * JPAD + k0 + c4];
            *(float4*)&sP[r * PSTR + c4] = make_float4(bv.x + mv.x, bv.y + mv.y,
                                                       bv.z + mv.z, bv.w + mv.w);
        }
        __syncthreads();

        // ---- S = Q @ K^T (registers); bf loads hit swizzled sK ----
        float sc[8][4] = {};
        const int swg = grp << 2;               // (n&7)<<2 for n = nt*8+grp
        #pragma unroll
        for (int ks = 0; ks < 4; ks++) {
            int kk = ks * 8 + tig;
            #pragma unroll
            for (int nt = 0; nt < 8; nt++) {
                int n = nt * 8 + grp;
                unsigned bf[2] = { uK[n * SKSTR + (kk ^ swg)],
                                   uK[n * SKSTR + ((kk + 4) ^ swg)] };
                mma8(sc[nt], aq[ks], bf);
            }
        }
        // ---- add staged bias+mask ----
        #pragma unroll
        for (int nt = 0; nt < 8; nt++) {
            float2 b0 = *(float2*)&sP[qr * PSTR + nt * 8 + 2 * tig];
            float2 b1 = *(float2*)&sP[(qr + 8) * PSTR + nt * 8 + 2 * tig];
            sc[nt][0] += b0.x; sc[nt][1] += b0.y;
            sc[nt][2] += b1.x; sc[nt][3] += b1.y;
        }
        // ---- online softmax update (per row-half) ----
        #pragma unroll
        for (int rh = 0; rh < 2; rh++) {
            float tmax = -1e30f;
            #pragma unroll
            for (int nt = 0; nt < 8; nt++)
                tmax = fmaxf(tmax, fmaxf(sc[nt][2 * rh], sc[nt][2 * rh + 1]));
            tmax = fmaxf(tmax, __shfl_xor_sync(0xffffffffu, tmax, 1));
            tmax = fmaxf(tmax, __shfl_xor_sync(0xffffffffu, tmax, 2));
            float mnew  = fmaxf(mrow[rh], tmax);
            float alpha = exp2f(mrow[rh] - mnew);
            mrow[rh] = mnew;
            float tsum = 0.f;
            #pragma unroll
            for (int nt = 0; nt < 8; nt++) {
                float p0 = exp2f(sc[nt][2 * rh]     - mnew);
                float p1 = exp2f(sc[nt][2 * rh + 1] - mnew);
                sc[nt][2 * rh] = p0; sc[nt][2 * rh + 1] = p1;
                tsum += p0 + p1;
            }
            tsum += __shfl_xor_sync(0xffffffffu, tsum, 1);
            tsum += __shfl_xor_sync(0xffffffffu, tsum, 2);
            lrow[rh] = lrow[rh] * alpha + tsum;
            #pragma unroll
            for (int nt = 0; nt < 4; nt++) {
                oacc[nt][2 * rh]     *= alpha;
                oacc[nt][2 * rh + 1] *= alpha;
            }
        }
        // ---- write P (tf32) to warp-private sP patch, re-fragment ----
        #pragma unroll
        for (int nt = 0; nt < 8; nt++) {
            *(float2*)&sP[qr * PSTR + nt * 8 + 2 * tig] = make_float2(
                __uint_as_float(f2tf(sc[nt][0])), __uint_as_float(f2tf(sc[nt][1])));
            *(float2*)&sP[(qr + 8) * PSTR + nt * 8 + 2 * tig] = make_float2(
                __uint_as_float(f2tf(sc[nt][2])), __uint_as_float(f2tf(sc[nt][3])));
        }
        __syncwarp();
        // ---- O += P @ V ----
        #pragma unroll
        for (int ks = 0; ks < 8; ks++) {
            int kk = ks * 8 + tig;
            unsigned af[4];
            af[0] = uP[qr * PSTR + kk];
            af[1] = uP[(qr + 8) * PSTR + kk];
            af[2] = uP[qr * PSTR + kk + 4];
            af[3] = uP[(qr + 8) * PSTR + kk + 4];
            #pragma unroll
            for (int nt = 0; nt < 4; nt++) {
                int d = nt * 8 + grp;
                unsigned bf[2] = { uV[kk * SVSTR + d], uV[(kk + 4) * SVSTR + d] };
                mma8(oacc[nt], af, bf);
            }
        }
        __syncthreads();
    }

    // ---- normalize + store ----
    float inv0 = 1.f / lrow[0];
    float inv1 = 1.f / lrow[1];
    int r0 = q0 + qr;
    #pragma unroll
    for (int nt = 0; nt < 4; nt++) {
        int d = h * HD + nt * 8 + 2 * tig;
        if (r0 < NTOK)
            *(float2*)&ao[(size_t)(b * NTOK + r0) * CDIM + d] =
                make_float2(oacc[nt][0] * inv0, oacc[nt][1] * inv0);
        if (r0 + 8 < NTOK)
            *(float2*)&ao[(size_t)(b * NTOK + r0 + 8) * CDIM + d] =
                make_float2(oacc[nt][2] * inv1, oacc[nt][3] * inv1);
    }
}

// ---------------------------------------------------------------------------
extern "C" void kernel_launch(void* const* d_in, const int* in_sizes, int n_in,
                              void* d_out, int out_size) {
    const float* x      = (const float*)d_in[0];
    const float* mask   = (const float*)d_in[1];
    const float* qkv_w  = (const float*)d_in[2];
    const float* qkv_b  = (const float*)d_in[3];
    const float* proj_w = (const float*)d_in[4];
    const float* proj_b = (const float*)d_in[5];
    const float* rpb    = (const float*)d_in[6];
    const int*   rel    = (const int*)d_in[7];
    float* out = (float*)d_out;

    float *p_qkv = nullptr, *p_ao = nullptr;
    cudaGetSymbolAddress((void**)&p_qkv, g_qkv);
    cudaGetSymbolAddress((void**)&p_ao,  g_ao);

    static bool attr_set = false;
    if (!attr_set) {
        cudaFuncSetAttribute(attn_flash, cudaFuncAttributeMaxDynamicSharedMemorySize,
                             FLASH_SMEM_BYTES);
        attr_set = true;
    }

    // 1) padded bias / mask precompute
    {
        int nb = HEADS * NTOK * JPAD;
        padb_kernel<<<(nb + 255) / 256, 256>>>(rpb, rel);
        int nm = NWIN * NTOK * JPAD;
        padm_kernel<<<(nm + 255) / 256, 256>>>(mask);
    }
    // 2) QKV GEMM
    {
        dim3 grid(C3 / BN, MTOT / BM);
        gemm_tc<CDIM><<<grid, 256>>>(x, qkv_w, qkv_b, p_qkv, MTOT, C3);
    }
    // 3) flash attention
    {
        dim3 grid(3, B_TOT * HEADS);
        attn_flash<<<grid, 256, FLASH_SMEM_BYTES>>>(p_qkv, p_ao);
    }
    // 4) proj GEMM
    {
        dim3 grid(CDIM / BN, MTOT / BM);
        gemm_tc<CDIM><<<grid, 256>>>(p_ao, proj_w, proj_b, out, MTOT, CDIM);
    }
}

// round 8
// speedup vs baseline: 1.1215x; 1.1215x over previous
#include <cuda_runtime.h>
#include <math.h>

#define B_TOT 128
#define NWIN  32
#define NTOK  343
#define HEADS 6
#define HD    32
#define CDIM  192
#define C3    576
#define MTOT  (B_TOT * NTOK)   // 43904
#define JPAD  384
#define L2E   1.4426950408889634f

// Scratch (no allocations allowed)
__device__ float g_qkv[MTOT * C3];                     // 101.2 MB
__device__ float g_ao [MTOT * CDIM];                   //  33.7 MB
__device__ float g_biasp[HEADS * NTOK * JPAD];         //   3.2 MB (L2-resident, *L2E, padded)
__device__ float g_maskp[NWIN  * NTOK * JPAD];         //  16.9 MB (L2-resident, *L2E, padded)

// ---------------------------------------------------------------------------
// tf32 helpers
// ---------------------------------------------------------------------------
__device__ __forceinline__ unsigned f2tf(float x) {
    unsigned r; asm("cvt.rna.tf32.f32 %0, %1;" : "=r"(r) : "f"(x)); return r;
}
__device__ __forceinline__ void mma8(float* c, const unsigned* a, const unsigned* b) {
    asm("mma.sync.aligned.m16n8k8.row.col.f32.tf32.tf32.f32 "
        "{%0,%1,%2,%3}, {%4,%5,%6,%7}, {%8,%9}, {%0,%1,%2,%3};"
        : "+f"(c[0]), "+f"(c[1]), "+f"(c[2]), "+f"(c[3])
        : "r"(a[0]), "r"(a[1]), "r"(a[2]), "r"(a[3]), "r"(b[0]), "r"(b[1]));
}

// ---------------------------------------------------------------------------
// Precompute padded, log2e-scaled bias and mask tables
// ---------------------------------------------------------------------------
__global__ void padb_kernel(const float* __restrict__ table,
                            const int* __restrict__ rel) {
    int idx = blockIdx.x * blockDim.x + threadIdx.x;
    if (idx >= HEADS * NTOK * JPAD) return;
    int j  = idx % JPAD;
    int hi = idx / JPAD;
    int i  = hi % NTOK, h = hi / NTOK;
    g_biasp[idx] = (j < NTOK) ? table[rel[i * NTOK + j] * HEADS + h] * L2E : -1e30f;
}
__global__ void padm_kernel(const float* __restrict__ mask) {
    int idx = blockIdx.x * blockDim.x + threadIdx.x;
    if (idx >= NWIN * NTOK * JPAD) return;
    int j  = idx % JPAD;
    int wi = idx / JPAD;
    int i  = wi % NTOK, w = wi / NTOK;
    g_maskp[idx] = (j < NTOK) ? mask[((size_t)w * NTOK + i) * NTOK + j] * L2E : -1e30f;
}

// ---------------------------------------------------------------------------
// Pipelined tensor-core GEMM (unchanged from R6)
// ---------------------------------------------------------------------------
#define BM 128
#define BN 64
#define BK 16
#define SA_STR 136
#define SB_STR 72

template<int K>
__global__ __launch_bounds__(256) void gemm_tc(const float* __restrict__ X,
                                               const float* __restrict__ W,
                                               const float* __restrict__ bias,
                                               float* __restrict__ C,
                                               int M, int N) {
    __shared__ unsigned sA[2][BK][SA_STR];
    __shared__ unsigned sB[2][BK][SB_STR];
    const int m0 = blockIdx.y * BM, n0 = blockIdx.x * BN;
    const int t = threadIdx.x, lane = t & 31, warp = t >> 5;
    const int wm = warp >> 1, wn = warp & 1;
    const int grp = lane >> 2, tig = lane & 3;
    const int lr  = t >> 2;
    const int lk4 = (t & 3) * 4;

    const float* pA0 = &X[(size_t)(m0 + lr) * K + lk4];
    const float* pA1 = &X[(size_t)(m0 + lr + 64) * K + lk4];
    const float* pB  = &W[(size_t)(n0 + lr) * K + lk4];

    float4 ra0 = *(const float4*)pA0;
    float4 ra1 = *(const float4*)pA1;
    float4 rb  = *(const float4*)pB;
    {
        sA[0][lk4+0][lr] = f2tf(ra0.x); sA[0][lk4+1][lr] = f2tf(ra0.y);
        sA[0][lk4+2][lr] = f2tf(ra0.z); sA[0][lk4+3][lr] = f2tf(ra0.w);
        sA[0][lk4+0][lr+64] = f2tf(ra1.x); sA[0][lk4+1][lr+64] = f2tf(ra1.y);
        sA[0][lk4+2][lr+64] = f2tf(ra1.z); sA[0][lk4+3][lr+64] = f2tf(ra1.w);
        sB[0][lk4+0][lr] = f2tf(rb.x); sB[0][lk4+1][lr] = f2tf(rb.y);
        sB[0][lk4+2][lr] = f2tf(rb.z); sB[0][lk4+3][lr] = f2tf(rb.w);
    }
    __syncthreads();

    float acc[2][4][4] = {};
    constexpr int NCH = K / BK;

    #pragma unroll
    for (int ch = 0; ch < NCH; ch++) {
        const int p = ch & 1;
        if (ch + 1 < NCH) {
            ra0 = *(const float4*)(pA0 + (ch + 1) * BK);
            ra1 = *(const float4*)(pA1 + (ch + 1) * BK);
            rb  = *(const float4*)(pB  + (ch + 1) * BK);
        }
        #pragma unroll
        for (int ks = 0; ks < 2; ks++) {
            const int kk = ks * 8 + tig;
            unsigned af[2][4], bf[4][2];
            #pragma unroll
            for (int mt = 0; mt < 2; mt++) {
                int r = wm * 32 + mt * 16 + grp;
                af[mt][0] = sA[p][kk][r];     af[mt][1] = sA[p][kk][r + 8];
                af[mt][2] = sA[p][kk+4][r];   af[mt][3] = sA[p][kk+4][r + 8];
            }
            #pragma unroll
            for (int nt = 0; nt < 4; nt++) {
                int n = wn * 32 + nt * 8 + grp;
                bf[nt][0] = sB[p][kk][n];
                bf[nt][1] = sB[p][kk+4][n];
            }
            #pragma unroll
            for (int mt = 0; mt < 2; mt++)
                #pragma unroll
                for (int nt = 0; nt < 4; nt++)
                    mma8(acc[mt][nt], af[mt], bf[nt]);
        }
        if (ch + 1 < NCH) {
            const int q = 1 - p;
            sA[q][lk4+0][lr] = f2tf(ra0.x); sA[q][lk4+1][lr] = f2tf(ra0.y);
            sA[q][lk4+2][lr] = f2tf(ra0.z); sA[q][lk4+3][lr] = f2tf(ra0.w);
            sA[q][lk4+0][lr+64] = f2tf(ra1.x); sA[q][lk4+1][lr+64] = f2tf(ra1.y);
            sA[q][lk4+2][lr+64] = f2tf(ra1.z); sA[q][lk4+3][lr+64] = f2tf(ra1.w);
            sB[q][lk4+0][lr] = f2tf(rb.x); sB[q][lk4+1][lr] = f2tf(rb.y);
            sB[q][lk4+2][lr] = f2tf(rb.z); sB[q][lk4+3][lr] = f2tf(rb.w);
            __syncthreads();
        }
    }
    #pragma unroll
    for (int mt = 0; mt < 2; mt++) {
        #pragma unroll
        for (int nt = 0; nt < 4; nt++) {
            int r = m0 + wm * 32 + mt * 16 + grp;
            int n = n0 + wn * 32 + nt * 8 + 2 * tig;
            float b0 = bias[n], b1 = bias[n + 1];
            *(float2*)&C[(size_t)r * N + n] =
                make_float2(acc[mt][nt][0] + b0, acc[mt][nt][1] + b1);
            *(float2*)&C[(size_t)(r + 8) * N + n] =
                make_float2(acc[mt][nt][2] + b0, acc[mt][nt][3] + b1);
        }
    }
}

// ---------------------------------------------------------------------------
// Flash attention R8: R6 layout (no swizzle), bias+mask loaded straight into
// the S accumulator fragments (no smem staging round-trip), STS.128 staging.
// ---------------------------------------------------------------------------
#define QT    128
#define SKSTR 36
#define SVSTR 40
#define PSTR  68
#define FLASH_SMEM_BYTES ((128*PSTR + 64*SKSTR + 64*SVSTR) * 4)

__global__ __launch_bounds__(256, 2) void attn_flash(const float* __restrict__ qkv,
                                                     float* __restrict__ ao) {
    extern __shared__ float sm[];
    float* sP = sm;                  // [128][68]: Q staging, then P patch
    float* sK = sP + 128 * PSTR;     // [64][36]
    float* sV = sK + 64 * SKSTR;     // [64][40]
    unsigned* uP = (unsigned*)sP;
    unsigned* uK = (unsigned*)sK;
    unsigned* uV = (unsigned*)sV;

    const int bh = blockIdx.y, b = bh / HEADS, h = bh % HEADS;
    const int q0 = blockIdx.x * QT;
    const int w = b % NWIN;
    const int t = threadIdx.x, lane = t & 31, warp = t >> 5;
    const int grp = lane >> 2, tig = lane & 3;
    const float qs = 0.17677669529663687f * L2E;   // hd^-0.5 * log2(e)

    // ---- stage Q (scaled, tf32), STS.128 ----
    #pragma unroll
    for (int it = 0; it < 4; it++) {
        int f = it * 256 + t;
        int r = f >> 3, d = (f & 7) * 4;
        int n = q0 + r;
        float4 v = make_float4(0.f, 0.f, 0.f, 0.f);
        if (n < NTOK) v = *(const float4*)&qkv[(size_t)(b * NTOK + n) * C3 + h * HD + d];
        *(uint4*)&uP[r * 36 + d] = make_uint4(f2tf(v.x * qs), f2tf(v.y * qs),
                                              f2tf(v.z * qs), f2tf(v.w * qs));
    }
    __syncthreads();

    // ---- Q fragments (warp owns rows warp*16 .. +15) ----
    unsigned aq[4][4];
    const int qr = warp * 16 + grp;
    #pragma unroll
    for (int ks = 0; ks < 4; ks++) {
        int kk = ks * 8 + tig;
        aq[ks][0] = uP[qr * 36 + kk];
        aq[ks][1] = uP[(qr + 8) * 36 + kk];
        aq[ks][2] = uP[qr * 36 + kk + 4];
        aq[ks][3] = uP[(qr + 8) * 36 + kk + 4];
    }
    __syncthreads();   // sP now only holds the per-tile P patch

    float oacc[4][4] = {};
    float mrow[2] = {-1e30f, -1e30f};
    float lrow[2] = {0.f, 0.f};

    // per-thread gmem row pointers for bias/mask fragments (clamped rows)
    int i0 = q0 + qr;          if (i0 > NTOK - 1) i0 = NTOK - 1;
    int i1 = q0 + qr + 8;      if (i1 > NTOK - 1) i1 = NTOK - 1;
    const float* b0p = g_biasp + ((size_t)h * NTOK + i0) * JPAD + 2 * tig;
    const float* b1p = g_biasp + ((size_t)h * NTOK + i1) * JPAD + 2 * tig;
    const float* m0p = g_maskp + ((size_t)w * NTOK + i0) * JPAD + 2 * tig;
    const float* m1p = g_maskp + ((size_t)w * NTOK + i1) * JPAD + 2 * tig;

    for (int kt = 0; kt < 6; kt++) {
        const int k0 = kt * 64;
        // ---- stage K,V tiles, STS.128 ----
        #pragma unroll
        for (int it = 0; it < 2; it++) {
            int f = it * 256 + t;
            int r = f >> 3, d = (f & 7) * 4;
            int n = k0 + r;
            float4 kv = make_float4(0.f, 0.f, 0.f, 0.f);
            float4 vv = make_float4(0.f, 0.f, 0.f, 0.f);
            if (n < NTOK) {
                kv = *(const float4*)&qkv[(size_t)(b * NTOK + n) * C3 + CDIM + h * HD + d];
                vv = *(const float4*)&qkv[(size_t)(b * NTOK + n) * C3 + 2 * CDIM + h * HD + d];
            }
            *(uint4*)&uK[r * SKSTR + d] = make_uint4(f2tf(kv.x), f2tf(kv.y),
                                                     f2tf(kv.z), f2tf(kv.w));
            *(uint4*)&uV[r * SVSTR + d] = make_uint4(f2tf(vv.x), f2tf(vv.y),
                                                     f2tf(vv.z), f2tf(vv.w));
        }

        // ---- init S fragments with bias+mask from gmem (overlaps staging) ----
        float sc[8][4];
        #pragma unroll
        for (int nt = 0; nt < 8; nt++) {
            int jo = k0 + nt * 8;
            float2 bb0 = *(const float2*)&b0p[jo];
            float2 mm0 = *(const float2*)&m0p[jo];
            float2 bb1 = *(const float2*)&b1p[jo];
            float2 mm1 = *(const float2*)&m1p[jo];
            sc[nt][0] = bb0.x + mm0.x;
            sc[nt][1] = bb0.y + mm0.y;
            sc[nt][2] = bb1.x + mm1.x;
            sc[nt][3] = bb1.y + mm1.y;
        }
        __syncthreads();

        // ---- S += Q @ K^T ----
        #pragma unroll
        for (int ks = 0; ks < 4; ks++) {
            int kk = ks * 8 + tig;
            #pragma unroll
            for (int nt = 0; nt < 8; nt++) {
                int n = nt * 8 + grp;
                unsigned bf[2] = { uK[n * SKSTR + kk], uK[n * SKSTR + kk + 4] };
                mma8(sc[nt], aq[ks], bf);
            }
        }
        // ---- online softmax update (per row-half) ----
        #pragma unroll
        for (int rh = 0; rh < 2; rh++) {
            float tmax = -1e30f;
            #pragma unroll
            for (int nt = 0; nt < 8; nt++)
                tmax = fmaxf(tmax, fmaxf(sc[nt][2 * rh], sc[nt][2 * rh + 1]));
            tmax = fmaxf(tmax, __shfl_xor_sync(0xffffffffu, tmax, 1));
            tmax = fmaxf(tmax, __shfl_xor_sync(0xffffffffu, tmax, 2));
            float mnew  = fmaxf(mrow[rh], tmax);
            float alpha = exp2f(mrow[rh] - mnew);
            mrow[rh] = mnew;
            float tsum = 0.f;
            #pragma unroll
            for (int nt = 0; nt < 8; nt++) {
                float p0 = exp2f(sc[nt][2 * rh]     - mnew);
                float p1 = exp2f(sc[nt][2 * rh + 1] - mnew);
                sc[nt][2 * rh] = p0; sc[nt][2 * rh + 1] = p1;
                tsum += p0 + p1;
            }
            tsum += __shfl_xor_sync(0xffffffffu, tsum, 1);
            tsum += __shfl_xor_sync(0xffffffffu, tsum, 2);
            lrow[rh] = lrow[rh] * alpha + tsum;
            #pragma unroll
            for (int nt = 0; nt < 4; nt++) {
                oacc[nt][2 * rh]     *= alpha;
                oacc[nt][2 * rh + 1] *= alpha;
            }
        }
        // ---- write P (tf32) to warp-private sP patch, re-fragment ----
        #pragma unroll
        for (int nt = 0; nt < 8; nt++) {
            *(float2*)&sP[qr * PSTR + nt * 8 + 2 * tig] = make_float2(
                __uint_as_float(f2tf(sc[nt][0])), __uint_as_float(f2tf(sc[nt][1])));
            *(float2*)&sP[(qr + 8) * PSTR + nt * 8 + 2 * tig] = make_float2(
                __uint_as_float(f2tf(sc[nt][2])), __uint_as_float(f2tf(sc[nt][3])));
        }
        __syncwarp();
        // ---- O += P @ V ----
        #pragma unroll
        for (int ks = 0; ks < 8; ks++) {
            int kk = ks * 8 + tig;
            unsigned af[4];
            af[0] = uP[qr * PSTR + kk];
            af[1] = uP[(qr + 8) * PSTR + kk];
            af[2] = uP[qr * PSTR + kk + 4];
            af[3] = uP[(qr + 8) * PSTR + kk + 4];
            #pragma unroll
            for (int nt = 0; nt < 4; nt++) {
                int d = nt * 8 + grp;
                unsigned bf[2] = { uV[kk * SVSTR + d], uV[(kk + 4) * SVSTR + d] };
                mma8(oacc[nt], af, bf);
            }
        }
        __syncthreads();
    }

    // ---- normalize + store ----
    float inv0 = 1.f / lrow[0];
    float inv1 = 1.f / lrow[1];
    int r0 = q0 + qr;
    #pragma unroll
    for (int nt = 0; nt < 4; nt++) {
        int d = h * HD + nt * 8 + 2 * tig;
        if (r0 < NTOK)
            *(float2*)&ao[(size_t)(b * NTOK + r0) * CDIM + d] =
                make_float2(oacc[nt][0] * inv0, oacc[nt][1] * inv0);
        if (r0 + 8 < NTOK)
            *(float2*)&ao[(size_t)(b * NTOK + r0 + 8) * CDIM + d] =
                make_float2(oacc[nt][2] * inv1, oacc[nt][3] * inv1);
    }
}

// ---------------------------------------------------------------------------
extern "C" void kernel_launch(void* const* d_in, const int* in_sizes, int n_in,
                              void* d_out, int out_size) {
    const float* x      = (const float*)d_in[0];
    const float* mask   = (const float*)d_in[1];
    const float* qkv_w  = (const float*)d_in[2];
    const float* qkv_b  = (const float*)d_in[3];
    const float* proj_w = (const float*)d_in[4];
    const float* proj_b = (const float*)d_in[5];
    const float* rpb    = (const float*)d_in[6];
    const int*   rel    = (const int*)d_in[7];
    float* out = (float*)d_out;

    float *p_qkv = nullptr, *p_ao = nullptr;
    cudaGetSymbolAddress((void**)&p_qkv, g_qkv);
    cudaGetSymbolAddress((void**)&p_ao,  g_ao);

    static bool attr_set = false;
    if (!attr_set) {
        cudaFuncSetAttribute(attn_flash, cudaFuncAttributeMaxDynamicSharedMemorySize,
                             FLASH_SMEM_BYTES);
        attr_set = true;
    }

    // 1) padded bias / mask precompute
    {
        int nb = HEADS * NTOK * JPAD;
        padb_kernel<<<(nb + 255) / 256, 256>>>(rpb, rel);
        int nm = NWIN * NTOK * JPAD;
        padm_kernel<<<(nm + 255) / 256, 256>>>(mask);
    }
    // 2) QKV GEMM
    {
        dim3 grid(C3 / BN, MTOT / BM);
        gemm_tc<CDIM><<<grid, 256>>>(x, qkv_w, qkv_b, p_qkv, MTOT, C3);
    }
    // 3) flash attention
    {
        dim3 grid(3, B_TOT * HEADS);
        attn_flash<<<grid, 256, FLASH_SMEM_BYTES>>>(p_qkv, p_ao);
    }
    // 4) proj GEMM
    {
        dim3 grid(CDIM / BN, MTOT / BM);
        gemm_tc<CDIM><<<grid, 256>>>(p_ao, proj_w, proj_b, out, MTOT, CDIM);
    }
}

// round 9
// speedup vs baseline: 1.2166x; 1.0848x over previous
#include <cuda_runtime.h>
#include <math.h>

#define B_TOT 128
#define NWIN  32
#define NTOK  343
#define HEADS 6
#define HD    32
#define CDIM  192
#define C3    576
#define MTOT  (B_TOT * NTOK)   // 43904
#define JPAD  384
#define L2E   1.4426950408889634f
#define QSF   (0.17677669529663687f * L2E)   // hd^-0.5 * log2(e)

// Scratch (no allocations allowed)
__device__ float g_qkv[MTOT * C3];                     // tf32 bit patterns, Q pre-scaled
__device__ float g_ao [MTOT * CDIM];                   // fp32
__device__ float g_biasp[HEADS * NTOK * JPAD];         // *L2E, padded, L2-resident
__device__ float g_maskp[NWIN  * NTOK * JPAD];         // *L2E, padded, L2-resident

// ---------------------------------------------------------------------------
// helpers
// ---------------------------------------------------------------------------
__device__ __forceinline__ unsigned f2tf(float x) {
    unsigned r; asm("cvt.rna.tf32.f32 %0, %1;" : "=r"(r) : "f"(x)); return r;
}
__device__ __forceinline__ void mma8(float* c, const unsigned* a, const unsigned* b) {
    asm("mma.sync.aligned.m16n8k8.row.col.f32.tf32.tf32.f32 "
        "{%0,%1,%2,%3}, {%4,%5,%6,%7}, {%8,%9}, {%0,%1,%2,%3};"
        : "+f"(c[0]), "+f"(c[1]), "+f"(c[2]), "+f"(c[3])
        : "r"(a[0]), "r"(a[1]), "r"(a[2]), "r"(a[3]), "r"(b[0]), "r"(b[1]));
}
__device__ __forceinline__ void cp16(void* dst_smem, const void* src, int sz) {
    unsigned d = (unsigned)__cvta_generic_to_shared(dst_smem);
    asm volatile("cp.async.cg.shared.global [%0], [%1], 16, %2;"
                 :: "r"(d), "l"(src), "r"(sz) : "memory");
}
#define CP_COMMIT() asm volatile("cp.async.commit_group;" ::: "memory")
#define CP_WAIT0()  asm volatile("cp.async.wait_group 0;" ::: "memory")

// ---------------------------------------------------------------------------
// Precompute padded, log2e-scaled bias and mask tables
// ---------------------------------------------------------------------------
__global__ void padb_kernel(const float* __restrict__ table,
                            const int* __restrict__ rel) {
    int idx = blockIdx.x * blockDim.x + threadIdx.x;
    if (idx >= HEADS * NTOK * JPAD) return;
    int j  = idx % JPAD;
    int hi = idx / JPAD;
    int i  = hi % NTOK, h = hi / NTOK;
    g_biasp[idx] = (j < NTOK) ? table[rel[i * NTOK + j] * HEADS + h] * L2E : -1e30f;
}
__global__ void padm_kernel(const float* __restrict__ mask) {
    int idx = blockIdx.x * blockDim.x + threadIdx.x;
    if (idx >= NWIN * NTOK * JPAD) return;
    int j  = idx % JPAD;
    int wi = idx / JPAD;
    int i  = wi % NTOK, w = wi / NTOK;
    g_maskp[idx] = (j < NTOK) ? mask[((size_t)w * NTOK + i) * NTOK + j] * L2E : -1e30f;
}

// ---------------------------------------------------------------------------
// Pipelined tensor-core GEMM. TF32OUT: store tf32 bits, Q block scaled by QSF.
// ---------------------------------------------------------------------------
#define BM 128
#define BN 64
#define BK 16
#define SA_STR 136
#define SB_STR 72

template<int K, bool TF32OUT>
__global__ __launch_bounds__(256) void gemm_tc(const float* __restrict__ X,
                                               const float* __restrict__ W,
                                               const float* __restrict__ bias,
                                               float* __restrict__ C,
                                               int M, int N) {
    __shared__ unsigned sA[2][BK][SA_STR];
    __shared__ unsigned sB[2][BK][SB_STR];
    const int m0 = blockIdx.y * BM, n0 = blockIdx.x * BN;
    const int t = threadIdx.x, lane = t & 31, warp = t >> 5;
    const int wm = warp >> 1, wn = warp & 1;
    const int grp = lane >> 2, tig = lane & 3;
    const int lr  = t >> 2;
    const int lk4 = (t & 3) * 4;

    const float* pA0 = &X[(size_t)(m0 + lr) * K + lk4];
    const float* pA1 = &X[(size_t)(m0 + lr + 64) * K + lk4];
    const float* pB  = &W[(size_t)(n0 + lr) * K + lk4];

    float4 ra0 = *(const float4*)pA0;
    float4 ra1 = *(const float4*)pA1;
    float4 rb  = *(const float4*)pB;
    {
        sA[0][lk4+0][lr] = f2tf(ra0.x); sA[0][lk4+1][lr] = f2tf(ra0.y);
        sA[0][lk4+2][lr] = f2tf(ra0.z); sA[0][lk4+3][lr] = f2tf(ra0.w);
        sA[0][lk4+0][lr+64] = f2tf(ra1.x); sA[0][lk4+1][lr+64] = f2tf(ra1.y);
        sA[0][lk4+2][lr+64] = f2tf(ra1.z); sA[0][lk4+3][lr+64] = f2tf(ra1.w);
        sB[0][lk4+0][lr] = f2tf(rb.x); sB[0][lk4+1][lr] = f2tf(rb.y);
        sB[0][lk4+2][lr] = f2tf(rb.z); sB[0][lk4+3][lr] = f2tf(rb.w);
    }
    __syncthreads();

    float acc[2][4][4] = {};
    constexpr int NCH = K / BK;

    #pragma unroll
    for (int ch = 0; ch < NCH; ch++) {
        const int p = ch & 1;
        if (ch + 1 < NCH) {
            ra0 = *(const float4*)(pA0 + (ch + 1) * BK);
            ra1 = *(const float4*)(pA1 + (ch + 1) * BK);
            rb  = *(const float4*)(pB  + (ch + 1) * BK);
        }
        #pragma unroll
        for (int ks = 0; ks < 2; ks++) {
            const int kk = ks * 8 + tig;
            unsigned af[2][4], bf[4][2];
            #pragma unroll
            for (int mt = 0; mt < 2; mt++) {
                int r = wm * 32 + mt * 16 + grp;
                af[mt][0] = sA[p][kk][r];     af[mt][1] = sA[p][kk][r + 8];
                af[mt][2] = sA[p][kk+4][r];   af[mt][3] = sA[p][kk+4][r + 8];
            }
            #pragma unroll
            for (int nt = 0; nt < 4; nt++) {
                int n = wn * 32 + nt * 8 + grp;
                bf[nt][0] = sB[p][kk][n];
                bf[nt][1] = sB[p][kk+4][n];
            }
            #pragma unroll
            for (int mt = 0; mt < 2; mt++)
                #pragma unroll
                for (int nt = 0; nt < 4; nt++)
                    mma8(acc[mt][nt], af[mt], bf[nt]);
        }
        if (ch + 1 < NCH) {
            const int q = 1 - p;
            sA[q][lk4+0][lr] = f2tf(ra0.x); sA[q][lk4+1][lr] = f2tf(ra0.y);
            sA[q][lk4+2][lr] = f2tf(ra0.z); sA[q][lk4+3][lr] = f2tf(ra0.w);
            sA[q][lk4+0][lr+64] = f2tf(ra1.x); sA[q][lk4+1][lr+64] = f2tf(ra1.y);
            sA[q][lk4+2][lr+64] = f2tf(ra1.z); sA[q][lk4+3][lr+64] = f2tf(ra1.w);
            sB[q][lk4+0][lr] = f2tf(rb.x); sB[q][lk4+1][lr] = f2tf(rb.y);
            sB[q][lk4+2][lr] = f2tf(rb.z); sB[q][lk4+3][lr] = f2tf(rb.w);
            __syncthreads();
        }
    }
    const float s = TF32OUT ? ((n0 < CDIM) ? QSF : 1.0f) : 1.0f;
    #pragma unroll
    for (int mt = 0; mt < 2; mt++) {
        #pragma unroll
        for (int nt = 0; nt < 4; nt++) {
            int r = m0 + wm * 32 + mt * 16 + grp;
            int n = n0 + wn * 32 + nt * 8 + 2 * tig;
            float b0 = bias[n], b1 = bias[n + 1];
            float v00 = (acc[mt][nt][0] + b0) * s, v01 = (acc[mt][nt][1] + b1) * s;
            float v10 = (acc[mt][nt][2] + b0) * s, v11 = (acc[mt][nt][3] + b1) * s;
            if (TF32OUT) {
                *(uint2*)&C[(size_t)r * N + n]       = make_uint2(f2tf(v00), f2tf(v01));
                *(uint2*)&C[(size_t)(r + 8) * N + n] = make_uint2(f2tf(v10), f2tf(v11));
            } else {
                *(float2*)&C[(size_t)r * N + n]       = make_float2(v00, v01);
                *(float2*)&C[(size_t)(r + 8) * N + n] = make_float2(v10, v11);
            }
        }
    }
}

// ---------------------------------------------------------------------------
// Flash attention R9: tf32-native qkv, cp.async double-buffered K/V,
// double-buffered bias+mask staging, one __syncthreads per key tile.
// ---------------------------------------------------------------------------
#define QT    128
#define SKSTR 36
#define SVSTR 40
#define PSTR  68
// floats: 2*128*68 + 2*64*36 + 2*64*40 = 27136 -> 108544 bytes
#define FLASH_SMEM_BYTES ((2*128*PSTR + 2*64*SKSTR + 2*64*SVSTR) * 4)

__global__ __launch_bounds__(256, 2) void attn_flash(const float* __restrict__ qkv,
                                                     float* __restrict__ ao) {
    extern __shared__ float sm[];
    float* sP0 = sm;                        // [128][68]
    float* sP1 = sP0 + 128 * PSTR;          // [128][68]
    unsigned* uK0 = (unsigned*)(sP1 + 128 * PSTR);   // [64][36]
    unsigned* uK1 = uK0 + 64 * SKSTR;
    unsigned* uV0 = uK1 + 64 * SKSTR;                 // [64][40]
    unsigned* uV1 = uV0 + 64 * SVSTR;

    const int bh = blockIdx.y, b = bh / HEADS, h = bh % HEADS;
    const int q0 = blockIdx.x * QT;
    const int w = b % NWIN;
    const int t = threadIdx.x, lane = t & 31, warp = t >> 5;
    const int grp = lane >> 2, tig = lane & 3;
    const int qr = warp * 16 + grp;

    const float* biasp = g_biasp + (size_t)h * NTOK * JPAD;
    const float* maskp = g_maskp + (size_t)w * NTOK * JPAD;

    // ---- prologue: cp.async Q tile (already tf32+scaled) into sP0, stride 36 ----
    #pragma unroll
    for (int it = 0; it < 4; it++) {
        int f = it * 256 + t;
        int r = f >> 3, d4 = (f & 7) * 4;
        int n = q0 + r;
        int nn = (n < NTOK) ? n : 0;
        cp16(&sP0[r * 36 + d4],
             qkv + (size_t)(b * NTOK + nn) * C3 + h * HD + d4,
             (n < NTOK) ? 16 : 0);
    }
    CP_COMMIT();
    CP_WAIT0();
    __syncthreads();

    unsigned aq[4][4];
    {
        const unsigned* uQ = (const unsigned*)sP0;
        #pragma unroll
        for (int ks = 0; ks < 4; ks++) {
            int kk = ks * 8 + tig;
            aq[ks][0] = uQ[qr * 36 + kk];
            aq[ks][1] = uQ[(qr + 8) * 36 + kk];
            aq[ks][2] = uQ[qr * 36 + kk + 4];
            aq[ks][3] = uQ[(qr + 8) * 36 + kk + 4];
        }
    }
    __syncthreads();

    // ---- issue K/V tile 0 (cp.async), then stage bias tile 0 (overlaps) ----
    #pragma unroll
    for (int it = 0; it < 2; it++) {
        int f = it * 256 + t;
        int r = f >> 3, d4 = (f & 7) * 4;
        int n = r;                       // k0 = 0
        int sz = (n < NTOK) ? 16 : 0;
        const float* base = qkv + (size_t)(b * NTOK + n) * C3 + h * HD + d4;
        cp16(&uK0[r * SKSTR + d4], base + CDIM, sz);
        cp16(&uV0[r * SVSTR + d4], base + 2 * CDIM, sz);
    }
    CP_COMMIT();
    #pragma unroll
    for (int it = 0; it < 8; it++) {
        int f = it * 256 + t;
        int r = f >> 4, c4 = (f & 15) * 4;
        int i = q0 + r; if (i > NTOK - 1) i = NTOK - 1;
        float4 bv = *(const float4*)&biasp[i * JPAD + c4];
        float4 mv = *(const float4*)&maskp[i * JPAD + c4];
        *(float4*)&sP0[r * PSTR + c4] = make_float4(bv.x + mv.x, bv.y + mv.y,
                                                    bv.z + mv.z, bv.w + mv.w);
    }

    float oacc[4][4] = {};
    float mrow[2] = {-1e30f, -1e30f};
    float lrow[2] = {0.f, 0.f};

    for (int kt = 0; kt < 6; kt++) {
        float*    sPc = (kt & 1) ? sP1 : sP0;
        unsigned* uKc = (kt & 1) ? uK1 : uK0;
        unsigned* uVc = (kt & 1) ? uV1 : uV0;

        CP_WAIT0();          // K/V tile kt landed
        __syncthreads();     // + bias kt visible, prev buffers fully consumed

        if (kt < 5) {        // prefetch K/V tile kt+1 into the other buffer
            unsigned* uKn = (kt & 1) ? uK0 : uK1;
            unsigned* uVn = (kt & 1) ? uV0 : uV1;
            int k0n = (kt + 1) * 64;
            #pragma unroll
            for (int it = 0; it < 2; it++) {
                int f = it * 256 + t;
                int r = f >> 3, d4 = (f & 7) * 4;
                int n = k0n + r;
                int nn = (n < NTOK) ? n : 0;
                int sz = (n < NTOK) ? 16 : 0;
                const float* base = qkv + (size_t)(b * NTOK + nn) * C3 + h * HD + d4;
                cp16(&uKn[r * SKSTR + d4], base + CDIM, sz);
                cp16(&uVn[r * SVSTR + d4], base + 2 * CDIM, sz);
            }
            CP_COMMIT();
        }

        // ---- S init from staged bias+mask, then S += Q @ K^T ----
        float sc[8][4];
        #pragma unroll
        for (int nt = 0; nt < 8; nt++) {
            float2 b0 = *(float2*)&sPc[qr * PSTR + nt * 8 + 2 * tig];
            float2 b1 = *(float2*)&sPc[(qr + 8) * PSTR + nt * 8 + 2 * tig];
            sc[nt][0] = b0.x; sc[nt][1] = b0.y; sc[nt][2] = b1.x; sc[nt][3] = b1.y;
        }
        #pragma unroll
        for (int ks = 0; ks < 4; ks++) {
            int kk = ks * 8 + tig;
            #pragma unroll
            for (int nt = 0; nt < 8; nt++) {
                int n = nt * 8 + grp;
                unsigned bf[2] = { uKc[n * SKSTR + kk], uKc[n * SKSTR + kk + 4] };
                mma8(sc[nt], aq[ks], bf);
            }
        }
        // ---- online softmax update (per row-half) ----
        #pragma unroll
        for (int rh = 0; rh < 2; rh++) {
            float tmax = -1e30f;
            #pragma unroll
            for (int nt = 0; nt < 8; nt++)
                tmax = fmaxf(tmax, fmaxf(sc[nt][2 * rh], sc[nt][2 * rh + 1]));
            tmax = fmaxf(tmax, __shfl_xor_sync(0xffffffffu, tmax, 1));
            tmax = fmaxf(tmax, __shfl_xor_sync(0xffffffffu, tmax, 2));
            float mnew  = fmaxf(mrow[rh], tmax);
            float alpha = exp2f(mrow[rh] - mnew);
            mrow[rh] = mnew;
            float tsum = 0.f;
            #pragma unroll
            for (int nt = 0; nt < 8; nt++) {
                float p0 = exp2f(sc[nt][2 * rh]     - mnew);
                float p1 = exp2f(sc[nt][2 * rh + 1] - mnew);
                sc[nt][2 * rh] = p0; sc[nt][2 * rh + 1] = p1;
                tsum += p0 + p1;
            }
            tsum += __shfl_xor_sync(0xffffffffu, tsum, 1);
            tsum += __shfl_xor_sync(0xffffffffu, tsum, 2);
            lrow[rh] = lrow[rh] * alpha + tsum;
            #pragma unroll
            for (int nt = 0; nt < 4; nt++) {
                oacc[nt][2 * rh]     *= alpha;
                oacc[nt][2 * rh + 1] *= alpha;
            }
        }
        // ---- write P (tf32) into own warp rows of sPc ----
        #pragma unroll
        for (int nt = 0; nt < 8; nt++) {
            *(float2*)&sPc[qr * PSTR + nt * 8 + 2 * tig] = make_float2(
                __uint_as_float(f2tf(sc[nt][0])), __uint_as_float(f2tf(sc[nt][1])));
            *(float2*)&sPc[(qr + 8) * PSTR + nt * 8 + 2 * tig] = make_float2(
                __uint_as_float(f2tf(sc[nt][2])), __uint_as_float(f2tf(sc[nt][3])));
        }
        __syncwarp();

        // ---- stage bias+mask for tile kt+1 into the other sP (overlaps PV) ----
        if (kt < 5) {
            float* sPn = (kt & 1) ? sP0 : sP1;
            int k0n = (kt + 1) * 64;
            #pragma unroll
            for (int it = 0; it < 8; it++) {
                int f = it * 256 + t;
                int r = f >> 4, c4 = (f & 15) * 4;
                int i = q0 + r; if (i > NTOK - 1) i = NTOK - 1;
                float4 bv = *(const float4*)&biasp[i * JPAD + k0n + c4];
                float4 mv = *(const float4*)&maskp[i * JPAD + k0n + c4];
                *(float4*)&sPn[r * PSTR + c4] = make_float4(bv.x + mv.x, bv.y + mv.y,
                                                            bv.z + mv.z, bv.w + mv.w);
            }
        }

        // ---- O += P @ V ----
        const unsigned* uPc = (const unsigned*)sPc;
        #pragma unroll
        for (int ks = 0; ks < 8; ks++) {
            int kk = ks * 8 + tig;
            unsigned af[4];
            af[0] = uPc[qr * PSTR + kk];
            af[1] = uPc[(qr + 8) * PSTR + kk];
            af[2] = uPc[qr * PSTR + kk + 4];
            af[3] = uPc[(qr + 8) * PSTR + kk + 4];
            #pragma unroll
            for (int nt = 0; nt < 4; nt++) {
                int d = nt * 8 + grp;
                unsigned bf[2] = { uVc[kk * SVSTR + d], uVc[(kk + 4) * SVSTR + d] };
                mma8(oacc[nt], af, bf);
            }
        }
    }

    // ---- normalize + store ----
    float inv0 = 1.f / lrow[0];
    float inv1 = 1.f / lrow[1];
    int r0 = q0 + qr;
    #pragma unroll
    for (int nt = 0; nt < 4; nt++) {
        int d = h * HD + nt * 8 + 2 * tig;
        if (r0 < NTOK)
            *(float2*)&ao[(size_t)(b * NTOK + r0) * CDIM + d] =
                make_float2(oacc[nt][0] * inv0, oacc[nt][1] * inv0);
        if (r0 + 8 < NTOK)
            *(float2*)&ao[(size_t)(b * NTOK + r0 + 8) * CDIM + d] =
                make_float2(oacc[nt][2] * inv1, oacc[nt][3] * inv1);
    }
}

// ---------------------------------------------------------------------------
extern "C" void kernel_launch(void* const* d_in, const int* in_sizes, int n_in,
                              void* d_out, int out_size) {
    const float* x      = (const float*)d_in[0];
    const float* mask   = (const float*)d_in[1];
    const float* qkv_w  = (const float*)d_in[2];
    const float* qkv_b  = (const float*)d_in[3];
    const float* proj_w = (const float*)d_in[4];
    const float* proj_b = (const float*)d_in[5];
    const float* rpb    = (const float*)d_in[6];
    const int*   rel    = (const int*)d_in[7];
    float* out = (float*)d_out;

    float *p_qkv = nullptr, *p_ao = nullptr;
    cudaGetSymbolAddress((void**)&p_qkv, g_qkv);
    cudaGetSymbolAddress((void**)&p_ao,  g_ao);

    static bool attr_set = false;
    if (!attr_set) {
        cudaFuncSetAttribute(attn_flash, cudaFuncAttributeMaxDynamicSharedMemorySize,
                             FLASH_SMEM_BYTES);
        attr_set = true;
    }

    // 1) padded bias / mask precompute
    {
        int nb = HEADS * NTOK * JPAD;
        padb_kernel<<<(nb + 255) / 256, 256>>>(rpb, rel);
        int nm = NWIN * NTOK * JPAD;
        padm_kernel<<<(nm + 255) / 256, 256>>>(mask);
    }
    // 2) QKV GEMM -> tf32 bits, Q pre-scaled
    {
        dim3 grid(C3 / BN, MTOT / BM);
        gemm_tc<CDIM, true><<<grid, 256>>>(x, qkv_w, qkv_b, p_qkv, MTOT, C3);
    }
    // 3) flash attention
    {
        dim3 grid(3, B_TOT * HEADS);
        attn_flash<<<grid, 256, FLASH_SMEM_BYTES>>>(p_qkv, p_ao);
    }
    // 4) proj GEMM (fp32 out)
    {
        dim3 grid(CDIM / BN, MTOT / BM);
        gemm_tc<CDIM, false><<<grid, 256>>>(p_ao, proj_w, proj_b, out, MTOT, CDIM);
    }
}

// round 12
// speedup vs baseline: 1.7041x; 1.4008x over previous
#include <cuda_runtime.h>
#include <cuda_fp16.h>
#include <math.h>
#include <cstdint>

#define B_TOT 128
#define NWIN  32
#define NTOK  343
#define HEADS 6
#define HD    32
#define CDIM  192
#define C3    576
#define MTOT  (B_TOT * NTOK)   // 43904
#define JPAD  384
#define L2E   1.4426950408889634f
#define QSF   (0.17677669529663687f * L2E)   // hd^-0.5 * log2(e)

// Scratch (no allocations allowed)
__device__ __half g_qkv[MTOT * C3];                    // fp16, Q pre-scaled by QSF
__device__ __half g_ao [MTOT * CDIM];                  // fp16
__device__ float  g_biasp[HEADS * NTOK * JPAD];        // *L2E, padded, f32
__device__ float  g_maskp[NWIN  * NTOK * JPAD];        // *L2E, padded, f32

// ---------------------------------------------------------------------------
// helpers
// ---------------------------------------------------------------------------
__device__ __forceinline__ unsigned h2u(float a, float b) {
    __half2 h = __floats2half2_rn(a, b);
    return *(unsigned*)&h;
}
__device__ __forceinline__ void mmaf16(float* c, const unsigned* a, const unsigned* b) {
    asm("mma.sync.aligned.m16n8k16.row.col.f32.f16.f16.f32 "
        "{%0,%1,%2,%3}, {%4,%5,%6,%7}, {%8,%9}, {%0,%1,%2,%3};"
        : "+f"(c[0]), "+f"(c[1]), "+f"(c[2]), "+f"(c[3])
        : "r"(a[0]), "r"(a[1]), "r"(a[2]), "r"(a[3]), "r"(b[0]), "r"(b[1]));
}
__device__ __forceinline__ void ldm4t(unsigned& r0, unsigned& r1,
                                      unsigned& r2, unsigned& r3, uint32_t addr) {
    asm volatile("ldmatrix.sync.aligned.m8n8.x4.trans.shared.b16 {%0,%1,%2,%3}, [%4];"
                 : "=r"(r0), "=r"(r1), "=r"(r2), "=r"(r3) : "r"(addr));
}
__device__ __forceinline__ void cp16(void* dst_smem, const void* src) {
    unsigned d = (unsigned)__cvta_generic_to_shared(dst_smem);
    asm volatile("cp.async.cg.shared.global [%0], [%1], 16;"
                 :: "r"(d), "l"(src) : "memory");
}
#define CP_COMMIT() asm volatile("cp.async.commit_group;" ::: "memory")
#define CP_WAIT0()  asm volatile("cp.async.wait_group 0;" ::: "memory")
#define CP_WAIT1()  asm volatile("cp.async.wait_group 1;" ::: "memory")

// ---------------------------------------------------------------------------
// Precompute padded, log2e-scaled bias and mask tables (f32)
// ---------------------------------------------------------------------------
__global__ void padb_kernel(const float* __restrict__ table,
                            const int* __restrict__ rel) {
    int idx = blockIdx.x * blockDim.x + threadIdx.x;
    if (idx >= HEADS * NTOK * JPAD) return;
    int j  = idx % JPAD;
    int hi = idx / JPAD;
    int i  = hi % NTOK, h = hi / NTOK;
    g_biasp[idx] = (j < NTOK) ? table[rel[i * NTOK + j] * HEADS + h] * L2E : -1e30f;
}
__global__ void padm_kernel(const float* __restrict__ mask) {
    int idx = blockIdx.x * blockDim.x + threadIdx.x;
    if (idx >= NWIN * NTOK * JPAD) return;
    int j  = idx % JPAD;
    int wi = idx / JPAD;
    int i  = wi % NTOK, w = wi / NTOK;
    g_maskp[idx] = (j < NTOK) ? mask[((size_t)w * NTOK + i) * NTOK + j] * L2E : -1e30f;
}

// ---------------------------------------------------------------------------
// fp16 tensor-core GEMM: C[m][n] = sum_k X[m][k]*W[n][k] + bias[n]
// K = 192 (12 chunks of 16). smem [row][k-pair word], stride 12 -> fragment
// LDS banks (12*grp + tig) mod 32 all distinct (conflict-free).
// ---------------------------------------------------------------------------
template<bool IN_HALF, bool OUT_HALF>
__global__ __launch_bounds__(256) void gemm_f16(const void* __restrict__ Xv,
                                                const float* __restrict__ W,
                                                const float* __restrict__ bias,
                                                void* __restrict__ Cv, int N) {
    constexpr int K = CDIM;
    __shared__ unsigned sA[2][128][12];
    __shared__ unsigned sB[2][64][12];
    const int m0 = blockIdx.y * 128, n0 = blockIdx.x * 64;
    const int t = threadIdx.x, lane = t & 31, warp = t >> 5;
    const int wm = warp >> 1, wn = warp & 1;
    const int grp = lane >> 2, tig = lane & 3;

    const __half* Xh = (const __half*)Xv;
    const float*  Xf = (const float*)Xv;

    const int rAh = t >> 1, p0h = (t & 1) * 4;    // IN_HALF A staging
    const int rAf = t >> 2, lk4 = (t & 3) * 4;    // f32 A + B staging

    uint4  rh;
    float4 ra0, ra1, rb;

    auto ldregs = [&](int k0) {
        if (IN_HALF) {
            rh = *(const uint4*)(Xh + (size_t)(m0 + rAh) * K + k0 + p0h * 2);
        } else {
            ra0 = *(const float4*)(Xf + (size_t)(m0 + rAf) * K + k0 + lk4);
            ra1 = *(const float4*)(Xf + (size_t)(m0 + rAf + 64) * K + k0 + lk4);
        }
        rb = *(const float4*)(W + (size_t)(n0 + rAf) * K + k0 + lk4);
    };
    auto stregs = [&](int buf) {
        if (IN_HALF) {
            *(uint4*)&sA[buf][rAh][p0h] = rh;
        } else {
            sA[buf][rAf][lk4/2]          = h2u(ra0.x, ra0.y);
            sA[buf][rAf][lk4/2 + 1]      = h2u(ra0.z, ra0.w);
            sA[buf][rAf + 64][lk4/2]     = h2u(ra1.x, ra1.y);
            sA[buf][rAf + 64][lk4/2 + 1] = h2u(ra1.z, ra1.w);
        }
        sB[buf][rAf][lk4/2]     = h2u(rb.x, rb.y);
        sB[buf][rAf][lk4/2 + 1] = h2u(rb.z, rb.w);
    };

    ldregs(0);
    stregs(0);
    __syncthreads();

    float acc[2][4][4] = {};
    #pragma unroll
    for (int ch = 0; ch < 12; ch++) {
        const int p = ch & 1;
        if (ch < 11) ldregs((ch + 1) * 16);
        unsigned af[2][4], bf[4][2];
        #pragma unroll
        for (int mt = 0; mt < 2; mt++) {
            int r = wm * 32 + mt * 16 + grp;
            af[mt][0] = sA[p][r][tig];       af[mt][1] = sA[p][r + 8][tig];
            af[mt][2] = sA[p][r][tig + 4];   af[mt][3] = sA[p][r + 8][tig + 4];
        }
        #pragma unroll
        for (int nt = 0; nt < 4; nt++) {
            int n = wn * 32 + nt * 8 + grp;
            bf[nt][0] = sB[p][n][tig];
            bf[nt][1] = sB[p][n][tig + 4];
        }
        #pragma unroll
        for (int mt = 0; mt < 2; mt++)
            #pragma unroll
            for (int nt = 0; nt < 4; nt++)
                mmaf16(acc[mt][nt], af[mt], bf[nt]);
        if (ch < 11) {
            stregs(1 - p);
            __syncthreads();
        }
    }

    const float s = (OUT_HALF && n0 < CDIM) ? QSF : 1.0f;
    #pragma unroll
    for (int mt = 0; mt < 2; mt++) {
        #pragma unroll
        for (int nt = 0; nt < 4; nt++) {
            int r = m0 + wm * 32 + mt * 16 + grp;
            int n = n0 + wn * 32 + nt * 8 + 2 * tig;
            float b0 = bias[n], b1 = bias[n + 1];
            float v00 = (acc[mt][nt][0] + b0) * s, v01 = (acc[mt][nt][1] + b1) * s;
            float v10 = (acc[mt][nt][2] + b0) * s, v11 = (acc[mt][nt][3] + b1) * s;
            if (OUT_HALF) {
                __half* Ch = (__half*)Cv;
                *(unsigned*)(Ch + (size_t)r * N + n)       = h2u(v00, v01);
                *(unsigned*)(Ch + (size_t)(r + 8) * N + n) = h2u(v10, v11);
            } else {
                float* Cf = (float*)Cv;
                *(float2*)(Cf + (size_t)r * N + n)       = make_float2(v00, v01);
                *(float2*)(Cf + (size_t)(r + 8) * N + n) = make_float2(v10, v11);
            }
        }
    }
}

// ---------------------------------------------------------------------------
// Flash attention: fp16 mma m16n8k16, fp32 softmax/accum, P stays in registers,
// V via ldmatrix.trans. Double-buffered K/V (cp.async) and bias+mask tiles.
// ---------------------------------------------------------------------------
#define SQW 20
#define SKW 20
#define SVW 20
#define SBW 68
#define W_BM0 0
#define W_BM1 (128 * SBW)
#define W_Q   (2 * 128 * SBW)
#define W_K0  (W_Q + 128 * SQW)
#define W_K1  (W_K0 + 64 * SKW)
#define W_V0  (W_K1 + 64 * SKW)
#define W_V1  (W_V0 + 64 * SVW)
#define FLASH_SMEM_BYTES ((W_V1 + 64 * SVW) * 4)   // 100352 bytes

__global__ __launch_bounds__(256, 2) void attn_flash(const __half* __restrict__ qkv,
                                                     __half* __restrict__ ao) {
    extern __shared__ unsigned us[];
    float* fs = (float*)us;

    const int bh = blockIdx.y, b = bh / HEADS, h = bh % HEADS;
    const int q0 = blockIdx.x * 128;
    const int w = b % NWIN;
    const int t = threadIdx.x, lane = t & 31, warp = t >> 5;
    const int grp = lane >> 2, tig = lane & 3;
    const int qr = warp * 16 + grp;

    const float* biasp = g_biasp + (size_t)h * NTOK * JPAD;
    const float* maskp = g_maskp + (size_t)w * NTOK * JPAD;

    // ---- Q stage (cp.async, rows clamped; dup rows masked at store) ----
    #pragma unroll
    for (int it = 0; it < 2; it++) {
        int f = it * 256 + t;
        int r = f >> 2, c = f & 3;
        int n = q0 + r; if (n > NTOK - 1) n = NTOK - 1;
        cp16(us + W_Q + r * SQW + c * 4,
             qkv + (size_t)(b * NTOK + n) * C3 + h * HD + c * 8);
    }
    CP_COMMIT();
    // ---- K/V tile 0 (rows clamped; dup keys killed by BM=-1e30 padding) ----
    {
        int r = t >> 2, c = t & 3;
        const __half* base = qkv + (size_t)(b * NTOK + r) * C3 + h * HD + c * 8;
        cp16(us + W_K0 + r * SKW + c * 4, base + CDIM);
        cp16(us + W_V0 + r * SVW + c * 4, base + 2 * CDIM);
    }
    CP_COMMIT();
    // ---- BM tile 0 (f32, coalesced) ----
    #pragma unroll
    for (int it = 0; it < 8; it++) {
        int f = it * 256 + t;
        int r = f >> 4, c4 = (f & 15) * 4;
        int i = q0 + r; if (i > NTOK - 1) i = NTOK - 1;
        float4 bv = *(const float4*)&biasp[(size_t)i * JPAD + c4];
        float4 mv = *(const float4*)&maskp[(size_t)i * JPAD + c4];
        *(float4*)&fs[W_BM0 + r * SBW + c4] = make_float4(bv.x + mv.x, bv.y + mv.y,
                                                          bv.z + mv.z, bv.w + mv.w);
    }
    CP_WAIT1();          // Q landed (KV0 may still be in flight)
    __syncthreads();

    // ---- Q fragments (HD=32 -> 2 k16 blocks) ----
    unsigned aq[2][4];
    #pragma unroll
    for (int ks = 0; ks < 2; ks++) {
        aq[ks][0] = us[W_Q + qr * SQW + ks * 8 + tig];
        aq[ks][1] = us[W_Q + (qr + 8) * SQW + ks * 8 + tig];
        aq[ks][2] = us[W_Q + qr * SQW + ks * 8 + tig + 4];
        aq[ks][3] = us[W_Q + (qr + 8) * SQW + ks * 8 + tig + 4];
    }

    float oacc[4][4] = {};
    float mrow[2] = {-1e30f, -1e30f};
    float lrow[2] = {0.f, 0.f};

    // ldmatrix lane geometry (constant across tiles)
    const int vk   = (lane & 7) + ((lane >> 3) & 1) * 8;   // k row within 16-block
    const int vdby = ((lane >> 4) << 3) * 2;               // d byte offset (0 or 16)

    for (int kt = 0; kt < 6; kt++) {
        const unsigned* uKc = us + ((kt & 1) ? W_K1 : W_K0);
        const float*    fBMc = fs + ((kt & 1) ? W_BM1 : W_BM0);
        const uint32_t  vbase = (uint32_t)__cvta_generic_to_shared(
                                    us + ((kt & 1) ? W_V1 : W_V0));

        CP_WAIT0();          // K/V tile kt landed
        __syncthreads();     // prev buffers fully consumed; BM kt visible

        if (kt < 5) {        // prefetch K/V tile kt+1
            int r = t >> 2, c = t & 3;
            int n = (kt + 1) * 64 + r; if (n > NTOK - 1) n = NTOK - 1;
            const __half* base = qkv + (size_t)(b * NTOK + n) * C3 + h * HD + c * 8;
            cp16(us + ((kt & 1) ? W_K0 : W_K1) + r * SKW + c * 4, base + CDIM);
            cp16(us + ((kt & 1) ? W_V0 : W_V1) + r * SVW + c * 4, base + 2 * CDIM);
            CP_COMMIT();
        }

        // ---- S init from BM (f32), then S += Q @ K^T ----
        float sc[8][4];
        #pragma unroll
        for (int nt = 0; nt < 8; nt++) {
            float2 b0 = *(float2*)&fBMc[qr * SBW + nt * 8 + 2 * tig];
            float2 b1 = *(float2*)&fBMc[(qr + 8) * SBW + nt * 8 + 2 * tig];
            sc[nt][0] = b0.x; sc[nt][1] = b0.y; sc[nt][2] = b1.x; sc[nt][3] = b1.y;
        }
        #pragma unroll
        for (int ks = 0; ks < 2; ks++) {
            #pragma unroll
            for (int nt = 0; nt < 8; nt++) {
                int n = nt * 8 + grp;
                unsigned bf[2] = { uKc[n * SKW + ks * 8 + tig],
                                   uKc[n * SKW + ks * 8 + tig + 4] };
                mmaf16(sc[nt], aq[ks], bf);
            }
        }
        // ---- online softmax update (per row-half) ----
        #pragma unroll
        for (int rh = 0; rh < 2; rh++) {
            float tmax = -1e30f;
            #pragma unroll
            for (int nt = 0; nt < 8; nt++)
                tmax = fmaxf(tmax, fmaxf(sc[nt][2 * rh], sc[nt][2 * rh + 1]));
            tmax = fmaxf(tmax, __shfl_xor_sync(0xffffffffu, tmax, 1));
            tmax = fmaxf(tmax, __shfl_xor_sync(0xffffffffu, tmax, 2));
            float mnew  = fmaxf(mrow[rh], tmax);
            float alpha = exp2f(mrow[rh] - mnew);
            mrow[rh] = mnew;
            float tsum = 0.f;
            #pragma unroll
            for (int nt = 0; nt < 8; nt++) {
                float p0 = exp2f(sc[nt][2 * rh]     - mnew);
                float p1 = exp2f(sc[nt][2 * rh + 1] - mnew);
                sc[nt][2 * rh] = p0; sc[nt][2 * rh + 1] = p1;
                tsum += p0 + p1;
            }
            tsum += __shfl_xor_sync(0xffffffffu, tsum, 1);
            tsum += __shfl_xor_sync(0xffffffffu, tsum, 2);
            lrow[rh] = lrow[rh] * alpha + tsum;
            #pragma unroll
            for (int nt = 0; nt < 4; nt++) {
                oacc[nt][2 * rh]     *= alpha;
                oacc[nt][2 * rh + 1] *= alpha;
            }
        }

        // ---- stage BM tile kt+1 into other buffer (overlaps PV) ----
        if (kt < 5) {
            float* fBMn = fs + ((kt & 1) ? W_BM0 : W_BM1);
            int k0n = (kt + 1) * 64;
            #pragma unroll
            for (int it = 0; it < 8; it++) {
                int f = it * 256 + t;
                int r = f >> 4, c4 = (f & 15) * 4;
                int i = q0 + r; if (i > NTOK - 1) i = NTOK - 1;
                float4 bv = *(const float4*)&biasp[(size_t)i * JPAD + k0n + c4];
                float4 mv = *(const float4*)&maskp[(size_t)i * JPAD + k0n + c4];
                *(float4*)&fBMn[r * SBW + c4] = make_float4(bv.x + mv.x, bv.y + mv.y,
                                                            bv.z + mv.z, bv.w + mv.w);
            }
        }

        // ---- O += P @ V : P packed in registers, V via ldmatrix.trans ----
        #pragma unroll
        for (int z = 0; z < 4; z++) {
            unsigned af[4];
            af[0] = h2u(sc[2*z][0],     sc[2*z][1]);
            af[1] = h2u(sc[2*z][2],     sc[2*z][3]);
            af[2] = h2u(sc[2*z+1][0],   sc[2*z+1][1]);
            af[3] = h2u(sc[2*z+1][2],   sc[2*z+1][3]);
            uint32_t a0 = vbase + (uint32_t)(z * 16 + vk) * (SVW * 4) + vdby;
            unsigned v0, v1, v2, v3, w0, w1, w2, w3;
            ldm4t(v0, v1, v2, v3, a0);          // d-octets 0,1
            ldm4t(w0, w1, w2, w3, a0 + 32);     // d-octets 2,3
            unsigned b0[2] = {v0, v1}, b1[2] = {v2, v3};
            unsigned b2[2] = {w0, w1}, b3[2] = {w2, w3};
            mmaf16(oacc[0], af, b0);
            mmaf16(oacc[1], af, b1);
            mmaf16(oacc[2], af, b2);
            mmaf16(oacc[3], af, b3);
        }
    }

    // ---- normalize + store (fp16) ----
    float inv0 = 1.f / lrow[0];
    float inv1 = 1.f / lrow[1];
    int r0 = q0 + qr;
    #pragma unroll
    for (int nt = 0; nt < 4; nt++) {
        int d = h * HD + nt * 8 + 2 * tig;
        if (r0 < NTOK)
            *(unsigned*)(ao + (size_t)(b * NTOK + r0) * CDIM + d) =
                h2u(oacc[nt][0] * inv0, oacc[nt][1] * inv0);
        if (r0 + 8 < NTOK)
            *(unsigned*)(ao + (size_t)(b * NTOK + r0 + 8) * CDIM + d) =
                h2u(oacc[nt][2] * inv1, oacc[nt][3] * inv1);
    }
}

// ---------------------------------------------------------------------------
extern "C" void kernel_launch(void* const* d_in, const int* in_sizes, int n_in,
                              void* d_out, int out_size) {
    const float* x      = (const float*)d_in[0];
    const float* mask   = (const float*)d_in[1];
    const float* qkv_w  = (const float*)d_in[2];
    const float* qkv_b  = (const float*)d_in[3];
    const float* proj_w = (const float*)d_in[4];
    const float* proj_b = (const float*)d_in[5];
    const float* rpb    = (const float*)d_in[6];
    const int*   rel    = (const int*)d_in[7];
    float* out = (float*)d_out;

    __half *p_qkv = nullptr, *p_ao = nullptr;
    cudaGetSymbolAddress((void**)&p_qkv, g_qkv);
    cudaGetSymbolAddress((void**)&p_ao,  g_ao);

    static bool attr_set = false;
    if (!attr_set) {
        cudaFuncSetAttribute(attn_flash, cudaFuncAttributeMaxDynamicSharedMemorySize,
                             FLASH_SMEM_BYTES);
        attr_set = true;
    }

    // 1) padded bias / mask precompute
    {
        int nb = HEADS * NTOK * JPAD;
        padb_kernel<<<(nb + 255) / 256, 256>>>(rpb, rel);
        int nm = NWIN * NTOK * JPAD;
        padm_kernel<<<(nm + 255) / 256, 256>>>(mask);
    }
    // 2) QKV GEMM: f32 in -> fp16 out (Q pre-scaled)
    {
        dim3 grid(C3 / 64, MTOT / 128);
        gemm_f16<false, true><<<grid, 256>>>(x, qkv_w, qkv_b, p_qkv, C3);
    }
    // 3) flash attention (fp16)
    {
        dim3 grid(3, B_TOT * HEADS);
        attn_flash<<<grid, 256, FLASH_SMEM_BYTES>>>(p_qkv, p_ao);
    }
    // 4) proj GEMM: fp16 in -> f32 out
    {
        dim3 grid(CDIM / 64, MTOT / 128);
        gemm_f16<true, false><<<grid, 256>>>(p_ao, proj_w, proj_b, out, CDIM);
    }
}

// round 13
// speedup vs baseline: 1.9186x; 1.1259x over previous
#include <cuda_runtime.h>
#include <cuda_fp16.h>
#include <math.h>
#include <cstdint>

#define B_TOT 128
#define NWIN  32
#define NTOK  343
#define HEADS 6
#define HD    32
#define CDIM  192
#define C3    576
#define MTOT  (B_TOT * NTOK)   // 43904
#define JPAD  384
#define L2E   1.4426950408889634f
#define QSF   (0.17677669529663687f * L2E)   // hd^-0.5 * log2(e)

// Scratch (no allocations allowed)
__device__ __half g_qkv[MTOT * C3];                    // fp16, Q pre-scaled by QSF
__device__ __half g_ao [MTOT * CDIM];                  // fp16
__device__ __half g_x16[MTOT * CDIM];                  // fp16 copy of x
__device__ __half g_wq16[C3 * CDIM];                   // fp16 qkv_w
__device__ __half g_wp16[CDIM * CDIM];                 // fp16 proj_w
__device__ float  g_biasp[HEADS * NTOK * JPAD];        // *L2E, padded, f32
__device__ float  g_maskp[NWIN  * NTOK * JPAD];        // *L2E, padded, f32

// ---------------------------------------------------------------------------
// helpers
// ---------------------------------------------------------------------------
__device__ __forceinline__ unsigned h2u(float a, float b) {
    __half2 h = __floats2half2_rn(a, b);
    return *(unsigned*)&h;
}
__device__ __forceinline__ void mmaf16(float* c, const unsigned* a, const unsigned* b) {
    asm("mma.sync.aligned.m16n8k16.row.col.f32.f16.f16.f32 "
        "{%0,%1,%2,%3}, {%4,%5,%6,%7}, {%8,%9}, {%0,%1,%2,%3};"
        : "+f"(c[0]), "+f"(c[1]), "+f"(c[2]), "+f"(c[3])
        : "r"(a[0]), "r"(a[1]), "r"(a[2]), "r"(a[3]), "r"(b[0]), "r"(b[1]));
}
__device__ __forceinline__ void ldm4t(unsigned& r0, unsigned& r1,
                                      unsigned& r2, unsigned& r3, uint32_t addr) {
    asm volatile("ldmatrix.sync.aligned.m8n8.x4.trans.shared.b16 {%0,%1,%2,%3}, [%4];"
                 : "=r"(r0), "=r"(r1), "=r"(r2), "=r"(r3) : "r"(addr));
}
__device__ __forceinline__ void cp16(void* dst_smem, const void* src) {
    unsigned d = (unsigned)__cvta_generic_to_shared(dst_smem);
    asm volatile("cp.async.cg.shared.global [%0], [%1], 16;"
                 :: "r"(d), "l"(src) : "memory");
}
#define CP_COMMIT() asm volatile("cp.async.commit_group;" ::: "memory")
#define CP_WAIT0()  asm volatile("cp.async.wait_group 0;" ::: "memory")
#define CP_WAIT1()  asm volatile("cp.async.wait_group 1;" ::: "memory")

// ---------------------------------------------------------------------------
// Fused prep: fp16 conversions + padded bias/mask tables (one launch)
// ---------------------------------------------------------------------------
#define NX_SEG  (MTOT * CDIM)         // 8,429,568
#define NWQ_SEG (C3 * CDIM)           //   110,592
#define NWP_SEG (CDIM * CDIM)         //    36,864
#define NB_SEG  (HEADS * NTOK * JPAD) //   790,272
#define NM_SEG  (NWIN * NTOK * JPAD)  // 4,214,784
#define PREP_TOTAL (NX_SEG + NWQ_SEG + NWP_SEG + NB_SEG + NM_SEG)

__global__ void prep_kernel(const float* __restrict__ x,
                            const float* __restrict__ qkv_w,
                            const float* __restrict__ proj_w,
                            const float* __restrict__ table,
                            const int* __restrict__ rel,
                            const float* __restrict__ mask) {
    int idx = blockIdx.x * blockDim.x + threadIdx.x;
    if (idx < NX_SEG) { g_x16[idx] = __float2half_rn(x[idx]); return; }
    idx -= NX_SEG;
    if (idx < NWQ_SEG) { g_wq16[idx] = __float2half_rn(qkv_w[idx]); return; }
    idx -= NWQ_SEG;
    if (idx < NWP_SEG) { g_wp16[idx] = __float2half_rn(proj_w[idx]); return; }
    idx -= NWP_SEG;
    if (idx < NB_SEG) {
        int j  = idx % JPAD;
        int hi = idx / JPAD;
        int i  = hi % NTOK, h = hi / NTOK;
        g_biasp[idx] = (j < NTOK) ? table[rel[i * NTOK + j] * HEADS + h] * L2E : -1e30f;
        return;
    }
    idx -= NB_SEG;
    if (idx < NM_SEG) {
        int j  = idx % JPAD;
        int wi = idx / JPAD;
        int i  = wi % NTOK, w = wi / NTOK;
        g_maskp[idx] = (j < NTOK) ? mask[((size_t)w * NTOK + i) * NTOK + j] * L2E : -1e30f;
    }
}

// ---------------------------------------------------------------------------
// fp16 GEMM v2: full K=192 panel resident in smem via one-shot cp.async,
// ZERO in-loop syncs. C[m][n] = sum_k X[m][k]*W[n][k] + bias[n].
// Row stride 100 words -> fragment banks (4*grp + tig) all distinct.
// ---------------------------------------------------------------------------
#define G2_ASTR 100
#define G2_BOFF (128 * G2_ASTR)                 // word offset of B panel
#define G2_SMEM ((128 * G2_ASTR + 64 * G2_ASTR) * 4)   // 76800 bytes

template<bool OUT_HALF>
__global__ __launch_bounds__(256) void gemm_f16v2(const __half* __restrict__ X,
                                                  const __half* __restrict__ W,
                                                  const float* __restrict__ bias,
                                                  void* __restrict__ Cv, int N) {
    extern __shared__ unsigned us[];
    const int m0 = blockIdx.y * 128, n0 = blockIdx.x * 64;
    const int t = threadIdx.x, lane = t & 31, warp = t >> 5;
    const int wm = warp >> 1, wn = warp & 1;
    const int grp = lane >> 2, tig = lane & 3;

    // ---- one-shot cp.async of the whole K-panel ----
    // A: 128 rows x 24 16B-segments; B: 64 rows x 24 segments
    #pragma unroll
    for (int it = 0; it < 12; it++) {
        int f = it * 256 + t;
        int r = f / 24, seg = f % 24;
        cp16(us + r * G2_ASTR + seg * 4, X + (size_t)(m0 + r) * CDIM + seg * 8);
    }
    #pragma unroll
    for (int it = 0; it < 6; it++) {
        int f = it * 256 + t;
        int r = f / 24, seg = f % 24;
        cp16(us + G2_BOFF + r * G2_ASTR + seg * 4, W + (size_t)(n0 + r) * CDIM + seg * 8);
    }
    CP_COMMIT();
    CP_WAIT0();
    __syncthreads();

    // ---- pure mma stream: 12 chunks, no syncs ----
    float acc[2][4][4] = {};
    #pragma unroll
    for (int ch = 0; ch < 12; ch++) {
        const int kw = ch * 8;
        unsigned af[2][4], bf[4][2];
        #pragma unroll
        for (int mt = 0; mt < 2; mt++) {
            int r = wm * 32 + mt * 16 + grp;
            af[mt][0] = us[r * G2_ASTR + kw + tig];
            af[mt][1] = us[(r + 8) * G2_ASTR + kw + tig];
            af[mt][2] = us[r * G2_ASTR + kw + tig + 4];
            af[mt][3] = us[(r + 8) * G2_ASTR + kw + tig + 4];
        }
        #pragma unroll
        for (int nt = 0; nt < 4; nt++) {
            int n = wn * 32 + nt * 8 + grp;
            bf[nt][0] = us[G2_BOFF + n * G2_ASTR + kw + tig];
            bf[nt][1] = us[G2_BOFF + n * G2_ASTR + kw + tig + 4];
        }
        #pragma unroll
        for (int mt = 0; mt < 2; mt++)
            #pragma unroll
            for (int nt = 0; nt < 4; nt++)
                mmaf16(acc[mt][nt], af[mt], bf[nt]);
    }

    const float s = (OUT_HALF && n0 < CDIM) ? QSF : 1.0f;
    #pragma unroll
    for (int mt = 0; mt < 2; mt++) {
        #pragma unroll
        for (int nt = 0; nt < 4; nt++) {
            int r = m0 + wm * 32 + mt * 16 + grp;
            int n = n0 + wn * 32 + nt * 8 + 2 * tig;
            float b0 = bias[n], b1 = bias[n + 1];
            float v00 = (acc[mt][nt][0] + b0) * s, v01 = (acc[mt][nt][1] + b1) * s;
            float v10 = (acc[mt][nt][2] + b0) * s, v11 = (acc[mt][nt][3] + b1) * s;
            if (OUT_HALF) {
                __half* Ch = (__half*)Cv;
                *(unsigned*)(Ch + (size_t)r * N + n)       = h2u(v00, v01);
                *(unsigned*)(Ch + (size_t)(r + 8) * N + n) = h2u(v10, v11);
            } else {
                float* Cf = (float*)Cv;
                *(float2*)(Cf + (size_t)r * N + n)       = make_float2(v00, v01);
                *(float2*)(Cf + (size_t)(r + 8) * N + n) = make_float2(v10, v11);
            }
        }
    }
}

// ---------------------------------------------------------------------------
// Flash attention (unchanged from R12): fp16 mma, fp32 softmax/accum,
// P in registers, V via ldmatrix.trans, double-buffered K/V + BM tiles.
// ---------------------------------------------------------------------------
#define SQW 20
#define SKW 20
#define SVW 20
#define SBW 68
#define W_BM0 0
#define W_BM1 (128 * SBW)
#define W_Q   (2 * 128 * SBW)
#define W_K0  (W_Q + 128 * SQW)
#define W_K1  (W_K0 + 64 * SKW)
#define W_V0  (W_K1 + 64 * SKW)
#define W_V1  (W_V0 + 64 * SVW)
#define FLASH_SMEM_BYTES ((W_V1 + 64 * SVW) * 4)   // 100352 bytes

__global__ __launch_bounds__(256, 2) void attn_flash(const __half* __restrict__ qkv,
                                                     __half* __restrict__ ao) {
    extern __shared__ unsigned us[];
    float* fs = (float*)us;

    const int bh = blockIdx.y, b = bh / HEADS, h = bh % HEADS;
    const int q0 = blockIdx.x * 128;
    const int w = b % NWIN;
    const int t = threadIdx.x, lane = t & 31, warp = t >> 5;
    const int grp = lane >> 2, tig = lane & 3;
    const int qr = warp * 16 + grp;

    const float* biasp = g_biasp + (size_t)h * NTOK * JPAD;
    const float* maskp = g_maskp + (size_t)w * NTOK * JPAD;

    #pragma unroll
    for (int it = 0; it < 2; it++) {
        int f = it * 256 + t;
        int r = f >> 2, c = f & 3;
        int n = q0 + r; if (n > NTOK - 1) n = NTOK - 1;
        cp16(us + W_Q + r * SQW + c * 4,
             qkv + (size_t)(b * NTOK + n) * C3 + h * HD + c * 8);
    }
    CP_COMMIT();
    {
        int r = t >> 2, c = t & 3;
        const __half* base = qkv + (size_t)(b * NTOK + r) * C3 + h * HD + c * 8;
        cp16(us + W_K0 + r * SKW + c * 4, base + CDIM);
        cp16(us + W_V0 + r * SVW + c * 4, base + 2 * CDIM);
    }
    CP_COMMIT();
    #pragma unroll
    for (int it = 0; it < 8; it++) {
        int f = it * 256 + t;
        int r = f >> 4, c4 = (f & 15) * 4;
        int i = q0 + r; if (i > NTOK - 1) i = NTOK - 1;
        float4 bv = *(const float4*)&biasp[(size_t)i * JPAD + c4];
        float4 mv = *(const float4*)&maskp[(size_t)i * JPAD + c4];
        *(float4*)&fs[W_BM0 + r * SBW + c4] = make_float4(bv.x + mv.x, bv.y + mv.y,
                                                          bv.z + mv.z, bv.w + mv.w);
    }
    CP_WAIT1();
    __syncthreads();

    unsigned aq[2][4];
    #pragma unroll
    for (int ks = 0; ks < 2; ks++) {
        aq[ks][0] = us[W_Q + qr * SQW + ks * 8 + tig];
        aq[ks][1] = us[W_Q + (qr + 8) * SQW + ks * 8 + tig];
        aq[ks][2] = us[W_Q + qr * SQW + ks * 8 + tig + 4];
        aq[ks][3] = us[W_Q + (qr + 8) * SQW + ks * 8 + tig + 4];
    }

    float oacc[4][4] = {};
    float mrow[2] = {-1e30f, -1e30f};
    float lrow[2] = {0.f, 0.f};

    const int vk   = (lane & 7) + ((lane >> 3) & 1) * 8;
    const int vdby = ((lane >> 4) << 3) * 2;

    for (int kt = 0; kt < 6; kt++) {
        const unsigned* uKc = us + ((kt & 1) ? W_K1 : W_K0);
        const float*    fBMc = fs + ((kt & 1) ? W_BM1 : W_BM0);
        const uint32_t  vbase = (uint32_t)__cvta_generic_to_shared(
                                    us + ((kt & 1) ? W_V1 : W_V0));

        CP_WAIT0();
        __syncthreads();

        if (kt < 5) {
            int r = t >> 2, c = t & 3;
            int n = (kt + 1) * 64 + r; if (n > NTOK - 1) n = NTOK - 1;
            const __half* base = qkv + (size_t)(b * NTOK + n) * C3 + h * HD + c * 8;
            cp16(us + ((kt & 1) ? W_K0 : W_K1) + r * SKW + c * 4, base + CDIM);
            cp16(us + ((kt & 1) ? W_V0 : W_V1) + r * SVW + c * 4, base + 2 * CDIM);
            CP_COMMIT();
        }

        float sc[8][4];
        #pragma unroll
        for (int nt = 0; nt < 8; nt++) {
            float2 b0 = *(float2*)&fBMc[qr * SBW + nt * 8 + 2 * tig];
            float2 b1 = *(float2*)&fBMc[(qr + 8) * SBW + nt * 8 + 2 * tig];
            sc[nt][0] = b0.x; sc[nt][1] = b0.y; sc[nt][2] = b1.x; sc[nt][3] = b1.y;
        }
        #pragma unroll
        for (int ks = 0; ks < 2; ks++) {
            #pragma unroll
            for (int nt = 0; nt < 8; nt++) {
                int n = nt * 8 + grp;
                unsigned bf[2] = { uKc[n * SKW + ks * 8 + tig],
                                   uKc[n * SKW + ks * 8 + tig + 4] };
                mmaf16(sc[nt], aq[ks], bf);
            }
        }
        #pragma unroll
        for (int rh = 0; rh < 2; rh++) {
            float tmax = -1e30f;
            #pragma unroll
            for (int nt = 0; nt < 8; nt++)
                tmax = fmaxf(tmax, fmaxf(sc[nt][2 * rh], sc[nt][2 * rh + 1]));
            tmax = fmaxf(tmax, __shfl_xor_sync(0xffffffffu, tmax, 1));
            tmax = fmaxf(tmax, __shfl_xor_sync(0xffffffffu, tmax, 2));
            float mnew  = fmaxf(mrow[rh], tmax);
            float alpha = exp2f(mrow[rh] - mnew);
            mrow[rh] = mnew;
            float tsum = 0.f;
            #pragma unroll
            for (int nt = 0; nt < 8; nt++) {
                float p0 = exp2f(sc[nt][2 * rh]     - mnew);
                float p1 = exp2f(sc[nt][2 * rh + 1] - mnew);
                sc[nt][2 * rh] = p0; sc[nt][2 * rh + 1] = p1;
                tsum += p0 + p1;
            }
            tsum += __shfl_xor_sync(0xffffffffu, tsum, 1);
            tsum += __shfl_xor_sync(0xffffffffu, tsum, 2);
            lrow[rh] = lrow[rh] * alpha + tsum;
            #pragma unroll
            for (int nt = 0; nt < 4; nt++) {
                oacc[nt][2 * rh]     *= alpha;
                oacc[nt][2 * rh + 1] *= alpha;
            }
        }

        if (kt < 5) {
            float* fBMn = fs + ((kt & 1) ? W_BM0 : W_BM1);
            int k0n = (kt + 1) * 64;
            #pragma unroll
            for (int it = 0; it < 8; it++) {
                int f = it * 256 + t;
                int r = f >> 4, c4 = (f & 15) * 4;
                int i = q0 + r; if (i > NTOK - 1) i = NTOK - 1;
                float4 bv = *(const float4*)&biasp[(size_t)i * JPAD + k0n + c4];
                float4 mv = *(const float4*)&maskp[(size_t)i * JPAD + k0n + c4];
                *(float4*)&fBMn[r * SBW + c4] = make_float4(bv.x + mv.x, bv.y + mv.y,
                                                            bv.z + mv.z, bv.w + mv.w);
            }
        }

        #pragma unroll
        for (int z = 0; z < 4; z++) {
            unsigned af[4];
            af[0] = h2u(sc[2*z][0],     sc[2*z][1]);
            af[1] = h2u(sc[2*z][2],     sc[2*z][3]);
            af[2] = h2u(sc[2*z+1][0],   sc[2*z+1][1]);
            af[3] = h2u(sc[2*z+1][2],   sc[2*z+1][3]);
            uint32_t a0 = vbase + (uint32_t)(z * 16 + vk) * (SVW * 4) + vdby;
            unsigned v0, v1, v2, v3, w0, w1, w2, w3;
            ldm4t(v0, v1, v2, v3, a0);
            ldm4t(w0, w1, w2, w3, a0 + 32);
            unsigned b0[2] = {v0, v1}, b1[2] = {v2, v3};
            unsigned b2[2] = {w0, w1}, b3[2] = {w2, w3};
            mmaf16(oacc[0], af, b0);
            mmaf16(oacc[1], af, b1);
            mmaf16(oacc[2], af, b2);
            mmaf16(oacc[3], af, b3);
        }
    }

    float inv0 = 1.f / lrow[0];
    float inv1 = 1.f / lrow[1];
    int r0 = q0 + qr;
    #pragma unroll
    for (int nt = 0; nt < 4; nt++) {
        int d = h * HD + nt * 8 + 2 * tig;
        if (r0 < NTOK)
            *(unsigned*)(ao + (size_t)(b * NTOK + r0) * CDIM + d) =
                h2u(oacc[nt][0] * inv0, oacc[nt][1] * inv0);
        if (r0 + 8 < NTOK)
            *(unsigned*)(ao + (size_t)(b * NTOK + r0 + 8) * CDIM + d) =
                h2u(oacc[nt][2] * inv1, oacc[nt][3] * inv1);
    }
}

// ---------------------------------------------------------------------------
extern "C" void kernel_launch(void* const* d_in, const int* in_sizes, int n_in,
                              void* d_out, int out_size) {
    const float* x      = (const float*)d_in[0];
    const float* mask   = (const float*)d_in[1];
    const float* qkv_w  = (const float*)d_in[2];
    const float* qkv_b  = (const float*)d_in[3];
    const float* proj_w = (const float*)d_in[4];
    const float* proj_b = (const float*)d_in[5];
    const float* rpb    = (const float*)d_in[6];
    const int*   rel    = (const int*)d_in[7];
    float* out = (float*)d_out;

    __half *p_qkv = nullptr, *p_ao = nullptr, *p_x16 = nullptr;
    __half *p_wq = nullptr, *p_wp = nullptr;
    cudaGetSymbolAddress((void**)&p_qkv, g_qkv);
    cudaGetSymbolAddress((void**)&p_ao,  g_ao);
    cudaGetSymbolAddress((void**)&p_x16, g_x16);
    cudaGetSymbolAddress((void**)&p_wq,  g_wq16);
    cudaGetSymbolAddress((void**)&p_wp,  g_wp16);

    static bool attr_set = false;
    if (!attr_set) {
        cudaFuncSetAttribute(attn_flash, cudaFuncAttributeMaxDynamicSharedMemorySize,
                             FLASH_SMEM_BYTES);
        cudaFuncSetAttribute(gemm_f16v2<true>, cudaFuncAttributeMaxDynamicSharedMemorySize,
                             G2_SMEM);
        cudaFuncSetAttribute(gemm_f16v2<false>, cudaFuncAttributeMaxDynamicSharedMemorySize,
                             G2_SMEM);
        attr_set = true;
    }

    // 1) fused prep: fp16 conversions + padded bias/mask
    prep_kernel<<<(PREP_TOTAL + 255) / 256, 256>>>(x, qkv_w, proj_w, rpb, rel, mask);
    // 2) QKV GEMM: fp16 in -> fp16 out (Q pre-scaled)
    {
        dim3 grid(C3 / 64, MTOT / 128);
        gemm_f16v2<true><<<grid, 256, G2_SMEM>>>(p_x16, p_wq, qkv_b, p_qkv, C3);
    }
    // 3) flash attention (fp16)
    {
        dim3 grid(3, B_TOT * HEADS);
        attn_flash<<<grid, 256, FLASH_SMEM_BYTES>>>(p_qkv, p_ao);
    }
    // 4) proj GEMM: fp16 in -> f32 out
    {
        dim3 grid(CDIM / 64, MTOT / 128);
        gemm_f16v2<false><<<grid, 256, G2_SMEM>>>(p_ao, p_wp, proj_b, out, CDIM);
    }
}

// round 14
// speedup vs baseline: 2.0513x; 1.0692x over previous
#include <cuda_runtime.h>
#include <cuda_fp16.h>
#include <math.h>
#include <cstdint>

#define B_TOT 128
#define NWIN  32
#define NTOK  343
#define HEADS 6
#define HD    32
#define CDIM  192
#define C3    576
#define MTOT  (B_TOT * NTOK)   // 43904
#define JPAD  384
#define L2E   1.4426950408889634f
#define QSF   (0.17677669529663687f * L2E)   // hd^-0.5 * log2(e)

// Scratch (no allocations allowed)
__device__ __half g_qkv[MTOT * C3];                    // fp16, Q pre-scaled by QSF
__device__ __half g_ao [MTOT * CDIM];                  // fp16
__device__ __half g_x16[MTOT * CDIM];                  // fp16 copy of x
__device__ __half g_wq16[C3 * CDIM];                   // fp16 qkv_w
__device__ __half g_wp16[CDIM * CDIM];                 // fp16 proj_w
__device__ __half g_bm16[NWIN * HEADS * NTOK * JPAD];  // fused (bias+mask)*L2E, fp16, padded

// ---------------------------------------------------------------------------
// helpers
// ---------------------------------------------------------------------------
__device__ __forceinline__ unsigned h2u(float a, float b) {
    __half2 h = __floats2half2_rn(a, b);
    return *(unsigned*)&h;
}
__device__ __forceinline__ void mmaf16(float* c, const unsigned* a, const unsigned* b) {
    asm("mma.sync.aligned.m16n8k16.row.col.f32.f16.f16.f32 "
        "{%0,%1,%2,%3}, {%4,%5,%6,%7}, {%8,%9}, {%0,%1,%2,%3};"
        : "+f"(c[0]), "+f"(c[1]), "+f"(c[2]), "+f"(c[3])
        : "r"(a[0]), "r"(a[1]), "r"(a[2]), "r"(a[3]), "r"(b[0]), "r"(b[1]));
}
__device__ __forceinline__ void ldm4t(unsigned& r0, unsigned& r1,
                                      unsigned& r2, unsigned& r3, uint32_t addr) {
    asm volatile("ldmatrix.sync.aligned.m8n8.x4.trans.shared.b16 {%0,%1,%2,%3}, [%4];"
                 : "=r"(r0), "=r"(r1), "=r"(r2), "=r"(r3) : "r"(addr));
}
__device__ __forceinline__ void cp16(void* dst_smem, const void* src) {
    unsigned d = (unsigned)__cvta_generic_to_shared(dst_smem);
    asm volatile("cp.async.cg.shared.global [%0], [%1], 16;"
                 :: "r"(d), "l"(src) : "memory");
}
#define CP_COMMIT() asm volatile("cp.async.commit_group;" ::: "memory")
#define CP_WAIT0()  asm volatile("cp.async.wait_group 0;" ::: "memory")
#define CP_WAIT1()  asm volatile("cp.async.wait_group 1;" ::: "memory")

// ---------------------------------------------------------------------------
// Fused prep: fp16 conversions + fused fp16 bias+mask table (one launch)
// ---------------------------------------------------------------------------
#define NX_SEG  (MTOT * CDIM)                  // 8,429,568
#define NWQ_SEG (C3 * CDIM)                    //   110,592
#define NWP_SEG (CDIM * CDIM)                  //    36,864
#define NBM_SEG (NWIN * HEADS * NTOK * JPAD)   // 25,288,704
#define PREP_TOTAL (NX_SEG + NWQ_SEG + NWP_SEG + NBM_SEG)

__global__ void prep_kernel(const float* __restrict__ x,
                            const float* __restrict__ qkv_w,
                            const float* __restrict__ proj_w,
                            const float* __restrict__ table,
                            const int* __restrict__ rel,
                            const float* __restrict__ mask) {
    int idx = blockIdx.x * blockDim.x + threadIdx.x;
    if (idx < NX_SEG) { g_x16[idx] = __float2half_rn(x[idx]); return; }
    idx -= NX_SEG;
    if (idx < NWQ_SEG) { g_wq16[idx] = __float2half_rn(qkv_w[idx]); return; }
    idx -= NWQ_SEG;
    if (idx < NWP_SEG) { g_wp16[idx] = __float2half_rn(proj_w[idx]); return; }
    idx -= NWP_SEG;
    if (idx < NBM_SEG) {
        int j  = idx % JPAD;
        int r  = idx / JPAD;
        int i  = r % NTOK;
        int wh = r / NTOK;
        int h  = wh % HEADS;
        int w  = wh / HEADS;
        float v = -30000.0f;
        if (j < NTOK)
            v = (table[rel[i * NTOK + j] * HEADS + h]
                 + mask[((size_t)w * NTOK + i) * NTOK + j]) * L2E;
        g_bm16[idx] = __float2half_rn(v);
    }
}

// ---------------------------------------------------------------------------
// fp16 GEMM v2 (unchanged from R13): full K=192 panel via one-shot cp.async,
// zero in-loop syncs.
// ---------------------------------------------------------------------------
#define G2_ASTR 100
#define G2_BOFF (128 * G2_ASTR)
#define G2_SMEM ((128 * G2_ASTR + 64 * G2_ASTR) * 4)   // 76800 bytes

template<bool OUT_HALF>
__global__ __launch_bounds__(256) void gemm_f16v2(const __half* __restrict__ X,
                                                  const __half* __restrict__ W,
                                                  const float* __restrict__ bias,
                                                  void* __restrict__ Cv, int N) {
    extern __shared__ unsigned us[];
    const int m0 = blockIdx.y * 128, n0 = blockIdx.x * 64;
    const int t = threadIdx.x, lane = t & 31, warp = t >> 5;
    const int wm = warp >> 1, wn = warp & 1;
    const int grp = lane >> 2, tig = lane & 3;

    #pragma unroll
    for (int it = 0; it < 12; it++) {
        int f = it * 256 + t;
        int r = f / 24, seg = f % 24;
        cp16(us + r * G2_ASTR + seg * 4, X + (size_t)(m0 + r) * CDIM + seg * 8);
    }
    #pragma unroll
    for (int it = 0; it < 6; it++) {
        int f = it * 256 + t;
        int r = f / 24, seg = f % 24;
        cp16(us + G2_BOFF + r * G2_ASTR + seg * 4, W + (size_t)(n0 + r) * CDIM + seg * 8);
    }
    CP_COMMIT();
    CP_WAIT0();
    __syncthreads();

    float acc[2][4][4] = {};
    #pragma unroll
    for (int ch = 0; ch < 12; ch++) {
        const int kw = ch * 8;
        unsigned af[2][4], bf[4][2];
        #pragma unroll
        for (int mt = 0; mt < 2; mt++) {
            int r = wm * 32 + mt * 16 + grp;
            af[mt][0] = us[r * G2_ASTR + kw + tig];
            af[mt][1] = us[(r + 8) * G2_ASTR + kw + tig];
            af[mt][2] = us[r * G2_ASTR + kw + tig + 4];
            af[mt][3] = us[(r + 8) * G2_ASTR + kw + tig + 4];
        }
        #pragma unroll
        for (int nt = 0; nt < 4; nt++) {
            int n = wn * 32 + nt * 8 + grp;
            bf[nt][0] = us[G2_BOFF + n * G2_ASTR + kw + tig];
            bf[nt][1] = us[G2_BOFF + n * G2_ASTR + kw + tig + 4];
        }
        #pragma unroll
        for (int mt = 0; mt < 2; mt++)
            #pragma unroll
            for (int nt = 0; nt < 4; nt++)
                mmaf16(acc[mt][nt], af[mt], bf[nt]);
    }

    const float s = (OUT_HALF && n0 < CDIM) ? QSF : 1.0f;
    #pragma unroll
    for (int mt = 0; mt < 2; mt++) {
        #pragma unroll
        for (int nt = 0; nt < 4; nt++) {
            int r = m0 + wm * 32 + mt * 16 + grp;
            int n = n0 + wn * 32 + nt * 8 + 2 * tig;
            float b0 = bias[n], b1 = bias[n + 1];
            float v00 = (acc[mt][nt][0] + b0) * s, v01 = (acc[mt][nt][1] + b1) * s;
            float v10 = (acc[mt][nt][2] + b0) * s, v11 = (acc[mt][nt][3] + b1) * s;
            if (OUT_HALF) {
                __half* Ch = (__half*)Cv;
                *(unsigned*)(Ch + (size_t)r * N + n)       = h2u(v00, v01);
                *(unsigned*)(Ch + (size_t)(r + 8) * N + n) = h2u(v10, v11);
            } else {
                float* Cf = (float*)Cv;
                *(float2*)(Cf + (size_t)r * N + n)       = make_float2(v00, v01);
                *(float2*)(Cf + (size_t)(r + 8) * N + n) = make_float2(v10, v11);
            }
        }
    }
}

// ---------------------------------------------------------------------------
// Flash attention R14: fused fp16 BM table loaded via cp.async (pure copy,
// same commit group as K/V), fp32 softmax/accum, P in registers,
// V via ldmatrix.trans. Smem 67.6 KB.
// ---------------------------------------------------------------------------
// word-offsets; BM rows are fp16 with 72-half stride (word stride 36)
#define SBH   72                     // BM row stride in halves
#define W_BM0 0                      // 128*36 = 4608 words per buffer
#define W_BM1 4608
#define W_Q   9216                   // stride 20 words
#define W_K0  (W_Q + 128 * 20)       // 11776
#define W_K1  (W_K0 + 64 * 20)       // 13056
#define W_V0  (W_K1 + 64 * 20)       // 14336
#define W_V1  (W_V0 + 64 * 20)       // 15616
#define FLASH_SMEM_BYTES ((W_V1 + 64 * 20) * 4)   // 67584 bytes
#define SQW 20
#define SKW 20
#define SVW 20

__global__ __launch_bounds__(256, 2) void attn_flash(const __half* __restrict__ qkv,
                                                     __half* __restrict__ ao) {
    extern __shared__ unsigned us[];
    __half* hs = (__half*)us;

    const int bh = blockIdx.y, b = bh / HEADS, h = bh % HEADS;
    const int q0 = blockIdx.x * 128;
    const int w = b % NWIN;
    const int t = threadIdx.x, lane = t & 31, warp = t >> 5;
    const int grp = lane >> 2, tig = lane & 3;
    const int qr = warp * 16 + grp;

    const __half* bmt = g_bm16 + (size_t)(w * HEADS + h) * NTOK * JPAD;

    // ---- Q stage (cp.async, rows clamped) ----
    #pragma unroll
    for (int it = 0; it < 2; it++) {
        int f = it * 256 + t;
        int r = f >> 2, c = f & 3;
        int n = q0 + r; if (n > NTOK - 1) n = NTOK - 1;
        cp16(us + W_Q + r * SQW + c * 4,
             qkv + (size_t)(b * NTOK + n) * C3 + h * HD + c * 8);
    }
    CP_COMMIT();
    // ---- K/V tile 0 + BM tile 0 (one group) ----
    {
        int r = t >> 2, c = t & 3;
        const __half* base = qkv + (size_t)(b * NTOK + r) * C3 + h * HD + c * 8;
        cp16(us + W_K0 + r * SKW + c * 4, base + CDIM);
        cp16(us + W_V0 + r * SVW + c * 4, base + 2 * CDIM);
    }
    #pragma unroll
    for (int it = 0; it < 4; it++) {
        int f = it * 256 + t;                 // 1024 segments: 128 rows x 8 segs
        int r = f >> 3, seg = f & 7;
        int i = q0 + r; if (i > NTOK - 1) i = NTOK - 1;
        cp16(hs + 2 * W_BM0 + r * SBH + seg * 8,
             bmt + (size_t)i * JPAD + seg * 8);
    }
    CP_COMMIT();
    CP_WAIT1();
    __syncthreads();

    // ---- Q fragments ----
    unsigned aq[2][4];
    #pragma unroll
    for (int ks = 0; ks < 2; ks++) {
        aq[ks][0] = us[W_Q + qr * SQW + ks * 8 + tig];
        aq[ks][1] = us[W_Q + (qr + 8) * SQW + ks * 8 + tig];
        aq[ks][2] = us[W_Q + qr * SQW + ks * 8 + tig + 4];
        aq[ks][3] = us[W_Q + (qr + 8) * SQW + ks * 8 + tig + 4];
    }

    float oacc[4][4] = {};
    float mrow[2] = {-1e30f, -1e30f};
    float lrow[2] = {0.f, 0.f};

    const int vk   = (lane & 7) + ((lane >> 3) & 1) * 8;
    const int vdby = ((lane >> 4) << 3) * 2;

    for (int kt = 0; kt < 6; kt++) {
        const unsigned* uKc = us + ((kt & 1) ? W_K1 : W_K0);
        const __half*  hBMc = hs + 2 * ((kt & 1) ? W_BM1 : W_BM0);
        const uint32_t vbase = (uint32_t)__cvta_generic_to_shared(
                                   us + ((kt & 1) ? W_V1 : W_V0));

        CP_WAIT0();          // K/V + BM tile kt landed
        __syncthreads();     // prev buffers fully consumed

        if (kt < 5) {        // prefetch K/V + BM tile kt+1 (one group)
            int k0n = (kt + 1) * 64;
            {
                int r = t >> 2, c = t & 3;
                int n = k0n + r; if (n > NTOK - 1) n = NTOK - 1;
                const __half* base = qkv + (size_t)(b * NTOK + n) * C3 + h * HD + c * 8;
                cp16(us + ((kt & 1) ? W_K0 : W_K1) + r * SKW + c * 4, base + CDIM);
                cp16(us + ((kt & 1) ? W_V0 : W_V1) + r * SVW + c * 4, base + 2 * CDIM);
            }
            __half* hBMn = hs + 2 * ((kt & 1) ? W_BM0 : W_BM1);
            #pragma unroll
            for (int it = 0; it < 4; it++) {
                int f = it * 256 + t;
                int r = f >> 3, seg = f & 7;
                int i = q0 + r; if (i > NTOK - 1) i = NTOK - 1;
                cp16(hBMn + r * SBH + seg * 8,
                     bmt + (size_t)i * JPAD + k0n + seg * 8);
            }
            CP_COMMIT();
        }

        // ---- S init from fp16 BM, then S += Q @ K^T ----
        float sc[8][4];
        #pragma unroll
        for (int nt = 0; nt < 8; nt++) {
            float2 b0 = __half22float2(
                *(const __half2*)(hBMc + qr * SBH + nt * 8 + 2 * tig));
            float2 b1 = __half22float2(
                *(const __half2*)(hBMc + (qr + 8) * SBH + nt * 8 + 2 * tig));
            sc[nt][0] = b0.x; sc[nt][1] = b0.y; sc[nt][2] = b1.x; sc[nt][3] = b1.y;
        }
        #pragma unroll
        for (int ks = 0; ks < 2; ks++) {
            #pragma unroll
            for (int nt = 0; nt < 8; nt++) {
                int n = nt * 8 + grp;
                unsigned bf[2] = { uKc[n * SKW + ks * 8 + tig],
                                   uKc[n * SKW + ks * 8 + tig + 4] };
                mmaf16(sc[nt], aq[ks], bf);
            }
        }
        // ---- online softmax update ----
        #pragma unroll
        for (int rh = 0; rh < 2; rh++) {
            float tmax = -1e30f;
            #pragma unroll
            for (int nt = 0; nt < 8; nt++)
                tmax = fmaxf(tmax, fmaxf(sc[nt][2 * rh], sc[nt][2 * rh + 1]));
            tmax = fmaxf(tmax, __shfl_xor_sync(0xffffffffu, tmax, 1));
            tmax = fmaxf(tmax, __shfl_xor_sync(0xffffffffu, tmax, 2));
            float mnew  = fmaxf(mrow[rh], tmax);
            float alpha = exp2f(mrow[rh] - mnew);
            mrow[rh] = mnew;
            float tsum = 0.f;
            #pragma unroll
            for (int nt = 0; nt < 8; nt++) {
                float p0 = exp2f(sc[nt][2 * rh]     - mnew);
                float p1 = exp2f(sc[nt][2 * rh + 1] - mnew);
                sc[nt][2 * rh] = p0; sc[nt][2 * rh + 1] = p1;
                tsum += p0 + p1;
            }
            tsum += __shfl_xor_sync(0xffffffffu, tsum, 1);
            tsum += __shfl_xor_sync(0xffffffffu, tsum, 2);
            lrow[rh] = lrow[rh] * alpha + tsum;
            #pragma unroll
            for (int nt = 0; nt < 4; nt++) {
                oacc[nt][2 * rh]     *= alpha;
                oacc[nt][2 * rh + 1] *= alpha;
            }
        }

        // ---- O += P @ V : P packed in registers, V via ldmatrix.trans ----
        #pragma unroll
        for (int z = 0; z < 4; z++) {
            unsigned af[4];
            af[0] = h2u(sc[2*z][0],     sc[2*z][1]);
            af[1] = h2u(sc[2*z][2],     sc[2*z][3]);
            af[2] = h2u(sc[2*z+1][0],   sc[2*z+1][1]);
            af[3] = h2u(sc[2*z+1][2],   sc[2*z+1][3]);
            uint32_t a0 = vbase + (uint32_t)(z * 16 + vk) * (SVW * 4) + vdby;
            unsigned v0, v1, v2, v3, w0, w1, w2, w3;
            ldm4t(v0, v1, v2, v3, a0);
            ldm4t(w0, w1, w2, w3, a0 + 32);
            unsigned b0[2] = {v0, v1}, b1[2] = {v2, v3};
            unsigned b2[2] = {w0, w1}, b3[2] = {w2, w3};
            mmaf16(oacc[0], af, b0);
            mmaf16(oacc[1], af, b1);
            mmaf16(oacc[2], af, b2);
            mmaf16(oacc[3], af, b3);
        }
    }

    // ---- normalize + store (fp16) ----
    float inv0 = 1.f / lrow[0];
    float inv1 = 1.f / lrow[1];
    int r0 = q0 + qr;
    #pragma unroll
    for (int nt = 0; nt < 4; nt++) {
        int d = h * HD + nt * 8 + 2 * tig;
        if (r0 < NTOK)
            *(unsigned*)(ao + (size_t)(b * NTOK + r0) * CDIM + d) =
                h2u(oacc[nt][0] * inv0, oacc[nt][1] * inv0);
        if (r0 + 8 < NTOK)
            *(unsigned*)(ao + (size_t)(b * NTOK + r0 + 8) * CDIM + d) =
                h2u(oacc[nt][2] * inv1, oacc[nt][3] * inv1);
    }
}

// ---------------------------------------------------------------------------
extern "C" void kernel_launch(void* const* d_in, const int* in_sizes, int n_in,
                              void* d_out, int out_size) {
    const float* x      = (const float*)d_in[0];
    const float* mask   = (const float*)d_in[1];
    const float* qkv_w  = (const float*)d_in[2];
    const float* qkv_b  = (const float*)d_in[3];
    const float* proj_w = (const float*)d_in[4];
    const float* proj_b = (const float*)d_in[5];
    const float* rpb    = (const float*)d_in[6];
    const int*   rel    = (const int*)d_in[7];
    float* out = (float*)d_out;

    __half *p_qkv = nullptr, *p_ao = nullptr, *p_x16 = nullptr;
    __half *p_wq = nullptr, *p_wp = nullptr;
    cudaGetSymbolAddress((void**)&p_qkv, g_qkv);
    cudaGetSymbolAddress((void**)&p_ao,  g_ao);
    cudaGetSymbolAddress((void**)&p_x16, g_x16);
    cudaGetSymbolAddress((void**)&p_wq,  g_wq16);
    cudaGetSymbolAddress((void**)&p_wp,  g_wp16);

    static bool attr_set = false;
    if (!attr_set) {
        cudaFuncSetAttribute(attn_flash, cudaFuncAttributeMaxDynamicSharedMemorySize,
                             FLASH_SMEM_BYTES);
        cudaFuncSetAttribute(gemm_f16v2<true>, cudaFuncAttributeMaxDynamicSharedMemorySize,
                             G2_SMEM);
        cudaFuncSetAttribute(gemm_f16v2<false>, cudaFuncAttributeMaxDynamicSharedMemorySize,
                             G2_SMEM);
        attr_set = true;
    }

    // 1) fused prep: fp16 conversions + fused fp16 BM table
    prep_kernel<<<(PREP_TOTAL + 255) / 256, 256>>>(x, qkv_w, proj_w, rpb, rel, mask);
    // 2) QKV GEMM: fp16 in -> fp16 out (Q pre-scaled)
    {
        dim3 grid(C3 / 64, MTOT / 128);
        gemm_f16v2<true><<<grid, 256, G2_SMEM>>>(p_x16, p_wq, qkv_b, p_qkv, C3);
    }
    // 3) flash attention (fp16, fused BM)
    {
        dim3 grid(3, B_TOT * HEADS);
        attn_flash<<<grid, 256, FLASH_SMEM_BYTES>>>(p_qkv, p_ao);
    }
    // 4) proj GEMM: fp16 in -> f32 out
    {
        dim3 grid(CDIM / 64, MTOT / 128);
        gemm_f16v2<false><<<grid, 256, G2_SMEM>>>(p_ao, p_wp, proj_b, out, CDIM);
    }
}

// round 15
// speedup vs baseline: 2.1014x; 1.0244x over previous
#include <cuda_runtime.h>
#include <cuda_fp16.h>
#include <math.h>
#include <cstdint>

#define B_TOT 128
#define NWIN  32
#define NTOK  343
#define HEADS 6
#define HD    32
#define CDIM  192
#define C3    576
#define MTOT  (B_TOT * NTOK)   // 43904
#define JPAD  384
#define L2E   1.4426950408889634f
#define QSF   (0.17677669529663687f * L2E)   // hd^-0.5 * log2(e)

// Scratch (no allocations allowed)
__device__ __half g_qkv[MTOT * C3];                    // fp16, Q pre-scaled by QSF
__device__ __half g_ao [MTOT * CDIM];                  // fp16
__device__ __half g_x16[MTOT * CDIM];                  // fp16 copy of x
__device__ __half g_wq16[C3 * CDIM];                   // fp16 qkv_w
__device__ __half g_wp16[CDIM * CDIM];                 // fp16 proj_w
__device__ __half g_bm16[NWIN * HEADS * NTOK * JPAD];  // fused (bias+mask)*L2E, fp16, padded

// ---------------------------------------------------------------------------
// helpers
// ---------------------------------------------------------------------------
__device__ __forceinline__ unsigned h2u(float a, float b) {
    __half2 h = __floats2half2_rn(a, b);
    return *(unsigned*)&h;
}
__device__ __forceinline__ float2 u2f2(unsigned u) {
    return __half22float2(*(__half2*)&u);
}
__device__ __forceinline__ void mmaf16(float* c, const unsigned* a, const unsigned* b) {
    asm("mma.sync.aligned.m16n8k16.row.col.f32.f16.f16.f32 "
        "{%0,%1,%2,%3}, {%4,%5,%6,%7}, {%8,%9}, {%0,%1,%2,%3};"
        : "+f"(c[0]), "+f"(c[1]), "+f"(c[2]), "+f"(c[3])
        : "r"(a[0]), "r"(a[1]), "r"(a[2]), "r"(a[3]), "r"(b[0]), "r"(b[1]));
}
__device__ __forceinline__ void ldm4(unsigned& r0, unsigned& r1,
                                     unsigned& r2, unsigned& r3, uint32_t addr) {
    asm volatile("ldmatrix.sync.aligned.m8n8.x4.shared.b16 {%0,%1,%2,%3}, [%4];"
                 : "=r"(r0), "=r"(r1), "=r"(r2), "=r"(r3) : "r"(addr));
}
__device__ __forceinline__ void ldm4t(unsigned& r0, unsigned& r1,
                                      unsigned& r2, unsigned& r3, uint32_t addr) {
    asm volatile("ldmatrix.sync.aligned.m8n8.x4.trans.shared.b16 {%0,%1,%2,%3}, [%4];"
                 : "=r"(r0), "=r"(r1), "=r"(r2), "=r"(r3) : "r"(addr));
}
__device__ __forceinline__ void cp16(void* dst_smem, const void* src) {
    unsigned d = (unsigned)__cvta_generic_to_shared(dst_smem);
    asm volatile("cp.async.cg.shared.global [%0], [%1], 16;"
                 :: "r"(d), "l"(src) : "memory");
}
#define CP_COMMIT() asm volatile("cp.async.commit_group;" ::: "memory")
#define CP_WAIT0()  asm volatile("cp.async.wait_group 0;" ::: "memory")
#define CP_WAIT1()  asm volatile("cp.async.wait_group 1;" ::: "memory")

// ---------------------------------------------------------------------------
// Fused prep: fp16 conversions + fused fp16 bias+mask table (one launch)
// ---------------------------------------------------------------------------
#define NX_SEG  (MTOT * CDIM)
#define NWQ_SEG (C3 * CDIM)
#define NWP_SEG (CDIM * CDIM)
#define NBM_SEG (NWIN * HEADS * NTOK * JPAD)
#define PREP_TOTAL (NX_SEG + NWQ_SEG + NWP_SEG + NBM_SEG)

__global__ void prep_kernel(const float* __restrict__ x,
                            const float* __restrict__ qkv_w,
                            const float* __restrict__ proj_w,
                            const float* __restrict__ table,
                            const int* __restrict__ rel,
                            const float* __restrict__ mask) {
    int idx = blockIdx.x * blockDim.x + threadIdx.x;
    if (idx < NX_SEG) { g_x16[idx] = __float2half_rn(x[idx]); return; }
    idx -= NX_SEG;
    if (idx < NWQ_SEG) { g_wq16[idx] = __float2half_rn(qkv_w[idx]); return; }
    idx -= NWQ_SEG;
    if (idx < NWP_SEG) { g_wp16[idx] = __float2half_rn(proj_w[idx]); return; }
    idx -= NWP_SEG;
    if (idx < NBM_SEG) {
        int j  = idx % JPAD;
        int r  = idx / JPAD;
        int i  = r % NTOK;
        int wh = r / NTOK;
        int h  = wh % HEADS;
        int w  = wh / HEADS;
        float v = -30000.0f;
        if (j < NTOK)
            v = (table[rel[i * NTOK + j] * HEADS + h]
                 + mask[((size_t)w * NTOK + i) * NTOK + j]) * L2E;
        g_bm16[idx] = __float2half_rn(v);
    }
}

// ---------------------------------------------------------------------------
// fp16 GEMM v3: full K=192 panel via one-shot cp.async, zero in-loop syncs,
// fragments via ldmatrix.x4 (4 per chunk instead of 24 LDS.32).
// ---------------------------------------------------------------------------
#define G2_ASTR 100
#define G2_BOFF (128 * G2_ASTR)
#define G2_SMEM ((128 * G2_ASTR + 64 * G2_ASTR) * 4)   // 76800 bytes

template<bool OUT_HALF>
__global__ __launch_bounds__(256) void gemm_f16v3(const __half* __restrict__ X,
                                                  const __half* __restrict__ W,
                                                  const float* __restrict__ bias,
                                                  void* __restrict__ Cv, int N) {
    extern __shared__ unsigned us[];
    const int m0 = blockIdx.y * 128, n0 = blockIdx.x * 64;
    const int t = threadIdx.x, lane = t & 31, warp = t >> 5;
    const int wm = warp >> 1, wn = warp & 1;
    const int grp = lane >> 2, tig = lane & 3;

    // ---- one-shot cp.async of the whole K-panel ----
    #pragma unroll
    for (int it = 0; it < 12; it++) {
        int f = it * 256 + t;
        int r = f / 24, seg = f % 24;
        cp16(us + r * G2_ASTR + seg * 4, X + (size_t)(m0 + r) * CDIM + seg * 8);
    }
    #pragma unroll
    for (int it = 0; it < 6; it++) {
        int f = it * 256 + t;
        int r = f / 24, seg = f % 24;
        cp16(us + G2_BOFF + r * G2_ASTR + seg * 4, W + (size_t)(n0 + r) * CDIM + seg * 8);
    }
    CP_COMMIT();
    CP_WAIT0();
    __syncthreads();

    // ---- ldmatrix lane geometry ----
    const int arow = (lane & 7) + ((lane >> 3) & 1) * 8;   // A: m-octet select
    const int akw  = (lane >> 4) * 4;                      // A: k-octet (words)
    const int brow = (lane & 7) + ((lane >> 4) & 1) * 8;   // B: n-octet select
    const int bkw  = ((lane >> 3) & 1) * 4;                // B: k-octet (words)
    uint32_t abase[2], bbase[2];
    #pragma unroll
    for (int mt = 0; mt < 2; mt++)
        abase[mt] = (uint32_t)__cvta_generic_to_shared(
            us + (wm * 32 + mt * 16 + arow) * G2_ASTR + akw);
    #pragma unroll
    for (int p = 0; p < 2; p++)
        bbase[p] = (uint32_t)__cvta_generic_to_shared(
            us + G2_BOFF + (wn * 32 + p * 16 + brow) * G2_ASTR + bkw);

    // ---- pure mma stream: 12 chunks, fragments via ldmatrix ----
    float acc[2][4][4] = {};
    #pragma unroll
    for (int ch = 0; ch < 12; ch++) {
        const uint32_t ko = (uint32_t)ch * 32;   // 8 words per chunk
        unsigned af[2][4], bf[4][2];
        ldm4(af[0][0], af[0][1], af[0][2], af[0][3], abase[0] + ko);
        ldm4(af[1][0], af[1][1], af[1][2], af[1][3], abase[1] + ko);
        ldm4(bf[0][0], bf[0][1], bf[1][0], bf[1][1], bbase[0] + ko);
        ldm4(bf[2][0], bf[2][1], bf[3][0], bf[3][1], bbase[1] + ko);
        #pragma unroll
        for (int mt = 0; mt < 2; mt++)
            #pragma unroll
            for (int nt = 0; nt < 4; nt++)
                mmaf16(acc[mt][nt], af[mt], bf[nt]);
    }

    const float s = (OUT_HALF && n0 < CDIM) ? QSF : 1.0f;
    #pragma unroll
    for (int mt = 0; mt < 2; mt++) {
        #pragma unroll
        for (int nt = 0; nt < 4; nt++) {
            int r = m0 + wm * 32 + mt * 16 + grp;
            int n = n0 + wn * 32 + nt * 8 + 2 * tig;
            float b0 = bias[n], b1 = bias[n + 1];
            float v00 = (acc[mt][nt][0] + b0) * s, v01 = (acc[mt][nt][1] + b1) * s;
            float v10 = (acc[mt][nt][2] + b0) * s, v11 = (acc[mt][nt][3] + b1) * s;
            if (OUT_HALF) {
                __half* Ch = (__half*)Cv;
                *(unsigned*)(Ch + (size_t)r * N + n)       = h2u(v00, v01);
                *(unsigned*)(Ch + (size_t)(r + 8) * N + n) = h2u(v10, v11);
            } else {
                float* Cf = (float*)Cv;
                *(float2*)(Cf + (size_t)r * N + n)       = make_float2(v00, v01);
                *(float2*)(Cf + (size_t)(r + 8) * N + n) = make_float2(v10, v11);
            }
        }
    }
}

// ---------------------------------------------------------------------------
// Flash attention R15: all fragment traffic via ldmatrix (K, V, BM),
// fp32 softmax/accum, P in registers. Smem 67.6 KB.
// ---------------------------------------------------------------------------
#define SBH   72                     // BM row stride in halves
#define W_BM0 0
#define W_BM1 4608
#define W_Q   9216
#define W_K0  (W_Q + 128 * 20)
#define W_K1  (W_K0 + 64 * 20)
#define W_V0  (W_K1 + 64 * 20)
#define W_V1  (W_V0 + 64 * 20)
#define FLASH_SMEM_BYTES ((W_V1 + 64 * 20) * 4)   // 67584 bytes
#define SQW 20
#define SKW 20
#define SVW 20

__global__ __launch_bounds__(256, 2) void attn_flash(const __half* __restrict__ qkv,
                                                     __half* __restrict__ ao) {
    extern __shared__ unsigned us[];
    __half* hs = (__half*)us;

    const int bh = blockIdx.y, b = bh / HEADS, h = bh % HEADS;
    const int q0 = blockIdx.x * 128;
    const int w = b % NWIN;
    const int t = threadIdx.x, lane = t & 31, warp = t >> 5;
    const int grp = lane >> 2, tig = lane & 3;
    const int qr = warp * 16 + grp;

    const __half* bmt = g_bm16 + (size_t)(w * HEADS + h) * NTOK * JPAD;

    // ---- Q stage ----
    #pragma unroll
    for (int it = 0; it < 2; it++) {
        int f = it * 256 + t;
        int r = f >> 2, c = f & 3;
        int n = q0 + r; if (n > NTOK - 1) n = NTOK - 1;
        cp16(us + W_Q + r * SQW + c * 4,
             qkv + (size_t)(b * NTOK + n) * C3 + h * HD + c * 8);
    }
    CP_COMMIT();
    // ---- K/V + BM tile 0 ----
    {
        int r = t >> 2, c = t & 3;
        const __half* base = qkv + (size_t)(b * NTOK + r) * C3 + h * HD + c * 8;
        cp16(us + W_K0 + r * SKW + c * 4, base + CDIM);
        cp16(us + W_V0 + r * SVW + c * 4, base + 2 * CDIM);
    }
    #pragma unroll
    for (int it = 0; it < 4; it++) {
        int f = it * 256 + t;
        int r = f >> 3, seg = f & 7;
        int i = q0 + r; if (i > NTOK - 1) i = NTOK - 1;
        cp16(hs + 2 * W_BM0 + r * SBH + seg * 8, bmt + (size_t)i * JPAD + seg * 8);
    }
    CP_COMMIT();
    CP_WAIT1();
    __syncthreads();

    // ---- Q fragments ----
    unsigned aq[2][4];
    #pragma unroll
    for (int ks = 0; ks < 2; ks++) {
        aq[ks][0] = us[W_Q + qr * SQW + ks * 8 + tig];
        aq[ks][1] = us[W_Q + (qr + 8) * SQW + ks * 8 + tig];
        aq[ks][2] = us[W_Q + qr * SQW + ks * 8 + tig + 4];
        aq[ks][3] = us[W_Q + (qr + 8) * SQW + ks * 8 + tig + 4];
    }

    float oacc[4][4] = {};
    float mrow[2] = {-1e30f, -1e30f};
    float lrow[2] = {0.f, 0.f};

    // ---- ldmatrix lane geometry ----
    const int arow = (lane & 7) + ((lane >> 3) & 1) * 8;   // A-style (BM)
    const int akh  = (lane >> 4) * 8;                      // BM col-octet (halves)
    const int brow = (lane & 7) + ((lane >> 4) & 1) * 8;   // B-style (K)
    const int bkw  = ((lane >> 3) & 1) * 4;                // K k-octet (words)
    const int vk   = (lane & 7) + ((lane >> 3) & 1) * 8;   // V trans rows
    const int vdby = ((lane >> 4) << 3) * 2;

    const uint32_t bm_lane_off = (uint32_t)((warp * 16 + arow) * SBH + akh) * 2;
    const uint32_t k_lane_off  = (uint32_t)(brow * SKW + bkw) * 4;

    for (int kt = 0; kt < 6; kt++) {
        const uint32_t kbase = (uint32_t)__cvta_generic_to_shared(
                                   us + ((kt & 1) ? W_K1 : W_K0)) + k_lane_off;
        const uint32_t bmb   = (uint32_t)__cvta_generic_to_shared(
                                   hs + 2 * ((kt & 1) ? W_BM1 : W_BM0)) + bm_lane_off;
        const uint32_t vbase = (uint32_t)__cvta_generic_to_shared(
                                   us + ((kt & 1) ? W_V1 : W_V0));

        CP_WAIT0();
        __syncthreads();

        if (kt < 5) {        // prefetch K/V + BM tile kt+1
            int k0n = (kt + 1) * 64;
            {
                int r = t >> 2, c = t & 3;
                int n = k0n + r; if (n > NTOK - 1) n = NTOK - 1;
                const __half* base = qkv + (size_t)(b * NTOK + n) * C3 + h * HD + c * 8;
                cp16(us + ((kt & 1) ? W_K0 : W_K1) + r * SKW + c * 4, base + CDIM);
                cp16(us + ((kt & 1) ? W_V0 : W_V1) + r * SVW + c * 4, base + 2 * CDIM);
            }
            __half* hBMn = hs + 2 * ((kt & 1) ? W_BM0 : W_BM1);
            #pragma unroll
            for (int it = 0; it < 4; it++) {
                int f = it * 256 + t;
                int r = f >> 3, seg = f & 7;
                int i = q0 + r; if (i > NTOK - 1) i = NTOK - 1;
                cp16(hBMn + r * SBH + seg * 8, bmt + (size_t)i * JPAD + k0n + seg * 8);
            }
            CP_COMMIT();
        }

        // ---- S init from BM via ldmatrix (fp16 -> f32) ----
        float sc[8][4];
        #pragma unroll
        for (int cb = 0; cb < 4; cb++) {
            unsigned r0, r1, r2, r3;
            ldm4(r0, r1, r2, r3, bmb + cb * 32);
            float2 f0 = u2f2(r0), f1 = u2f2(r1), f2 = u2f2(r2), f3 = u2f2(r3);
            sc[2*cb][0]   = f0.x; sc[2*cb][1]   = f0.y;
            sc[2*cb][2]   = f1.x; sc[2*cb][3]   = f1.y;
            sc[2*cb+1][0] = f2.x; sc[2*cb+1][1] = f2.y;
            sc[2*cb+1][2] = f3.x; sc[2*cb+1][3] = f3.y;
        }
        // ---- S += Q @ K^T : K fragments via ldmatrix ----
        #pragma unroll
        for (int ks = 0; ks < 2; ks++) {
            #pragma unroll
            for (int p = 0; p < 4; p++) {
                unsigned bf[4];
                ldm4(bf[0], bf[1], bf[2], bf[3], kbase + p * 1280 + ks * 32);
                mmaf16(sc[2*p],     aq[ks], bf);
                mmaf16(sc[2*p + 1], aq[ks], bf + 2);
            }
        }
        // ---- online softmax update ----
        #pragma unroll
        for (int rh = 0; rh < 2; rh++) {
            float tmax = -1e30f;
            #pragma unroll
            for (int nt = 0; nt < 8; nt++)
                tmax = fmaxf(tmax, fmaxf(sc[nt][2 * rh], sc[nt][2 * rh + 1]));
            tmax = fmaxf(tmax, __shfl_xor_sync(0xffffffffu, tmax, 1));
            tmax = fmaxf(tmax, __shfl_xor_sync(0xffffffffu, tmax, 2));
            float mnew  = fmaxf(mrow[rh], tmax);
            float alpha = exp2f(mrow[rh] - mnew);
            mrow[rh] = mnew;
            float tsum = 0.f;
            #pragma unroll
            for (int nt = 0; nt < 8; nt++) {
                float p0 = exp2f(sc[nt][2 * rh]     - mnew);
                float p1 = exp2f(sc[nt][2 * rh + 1] - mnew);
                sc[nt][2 * rh] = p0; sc[nt][2 * rh + 1] = p1;
                tsum += p0 + p1;
            }
            tsum += __shfl_xor_sync(0xffffffffu, tsum, 1);
            tsum += __shfl_xor_sync(0xffffffffu, tsum, 2);
            lrow[rh] = lrow[rh] * alpha + tsum;
            #pragma unroll
            for (int nt = 0; nt < 4; nt++) {
                oacc[nt][2 * rh]     *= alpha;
                oacc[nt][2 * rh + 1] *= alpha;
            }
        }

        // ---- O += P @ V : P packed in registers, V via ldmatrix.trans ----
        #pragma unroll
        for (int z = 0; z < 4; z++) {
            unsigned af[4];
            af[0] = h2u(sc[2*z][0],     sc[2*z][1]);
            af[1] = h2u(sc[2*z][2],     sc[2*z][3]);
            af[2] = h2u(sc[2*z+1][0],   sc[2*z+1][1]);
            af[3] = h2u(sc[2*z+1][2],   sc[2*z+1][3]);
            uint32_t a0 = vbase + (uint32_t)(z * 16 + vk) * (SVW * 4) + vdby;
            unsigned v0, v1, v2, v3, w0, w1, w2, w3;
            ldm4t(v0, v1, v2, v3, a0);
            ldm4t(w0, w1, w2, w3, a0 + 32);
            unsigned b0[2] = {v0, v1}, b1[2] = {v2, v3};
            unsigned b2[2] = {w0, w1}, b3[2] = {w2, w3};
            mmaf16(oacc[0], af, b0);
            mmaf16(oacc[1], af, b1);
            mmaf16(oacc[2], af, b2);
            mmaf16(oacc[3], af, b3);
        }
    }

    // ---- normalize + store (fp16) ----
    float inv0 = 1.f / lrow[0];
    float inv1 = 1.f / lrow[1];
    int r0 = q0 + qr;
    #pragma unroll
    for (int nt = 0; nt < 4; nt++) {
        int d = h * HD + nt * 8 + 2 * tig;
        if (r0 < NTOK)
            *(unsigned*)(ao + (size_t)(b * NTOK + r0) * CDIM + d) =
                h2u(oacc[nt][0] * inv0, oacc[nt][1] * inv0);
        if (r0 + 8 < NTOK)
            *(unsigned*)(ao + (size_t)(b * NTOK + r0 + 8) * CDIM + d) =
                h2u(oacc[nt][2] * inv1, oacc[nt][3] * inv1);
    }
}

// ---------------------------------------------------------------------------
extern "C" void kernel_launch(void* const* d_in, const int* in_sizes, int n_in,
                              void* d_out, int out_size) {
    const float* x      = (const float*)d_in[0];
    const float* mask   = (const float*)d_in[1];
    const float* qkv_w  = (const float*)d_in[2];
    const float* qkv_b  = (const float*)d_in[3];
    const float* proj_w = (const float*)d_in[4];
    const float* proj_b = (const float*)d_in[5];
    const float* rpb    = (const float*)d_in[6];
    const int*   rel    = (const int*)d_in[7];
    float* out = (float*)d_out;

    __half *p_qkv = nullptr, *p_ao = nullptr, *p_x16 = nullptr;
    __half *p_wq = nullptr, *p_wp = nullptr;
    cudaGetSymbolAddress((void**)&p_qkv, g_qkv);
    cudaGetSymbolAddress((void**)&p_ao,  g_ao);
    cudaGetSymbolAddress((void**)&p_x16, g_x16);
    cudaGetSymbolAddress((void**)&p_wq,  g_wq16);
    cudaGetSymbolAddress((void**)&p_wp,  g_wp16);

    static bool attr_set = false;
    if (!attr_set) {
        cudaFuncSetAttribute(attn_flash, cudaFuncAttributeMaxDynamicSharedMemorySize,
                             FLASH_SMEM_BYTES);
        cudaFuncSetAttribute(gemm_f16v3<true>, cudaFuncAttributeMaxDynamicSharedMemorySize,
                             G2_SMEM);
        cudaFuncSetAttribute(gemm_f16v3<false>, cudaFuncAttributeMaxDynamicSharedMemorySize,
                             G2_SMEM);
        attr_set = true;
    }

    // 1) fused prep
    prep_kernel<<<(PREP_TOTAL + 255) / 256, 256>>>(x, qkv_w, proj_w, rpb, rel, mask);
    // 2) QKV GEMM: fp16 in -> fp16 out (Q pre-scaled)
    {
        dim3 grid(C3 / 64, MTOT / 128);
        gemm_f16v3<true><<<grid, 256, G2_SMEM>>>(p_x16, p_wq, qkv_b, p_qkv, C3);
    }
    // 3) flash attention
    {
        dim3 grid(3, B_TOT * HEADS);
        attn_flash<<<grid, 256, FLASH_SMEM_BYTES>>>(p_qkv, p_ao);
    }
    // 4) proj GEMM: fp16 in -> f32 out
    {
        dim3 grid(CDIM / 64, MTOT / 128);
        gemm_f16v3<false><<<grid, 256, G2_SMEM>>>(p_ao, p_wp, proj_b, out, CDIM);
    }
}